// round 10
// baseline (speedup 1.0000x reference)
#include <cuda_runtime.h>
#include <cuda_fp16.h>
#include <cstdint>

#define NN 131072
#define NE 4194304
#define FI 64

// ---------------- scratch (device globals: no allocation allowed) ----------
__device__ float  g_deg [NN];        // degree, then dinv in-place
__device__ int    g_cnt [NN];        // in-degree histogram (by dst)
__device__ int    g_off [NN + 1];    // CSR row offsets (by dst)
__device__ int    g_rank[NE];        // per-edge rank within its dst row
__device__ int2   g_edge[NE];        // CSR record: {src, weight-bits}
__device__ __half g_xh[NN * FI];     // x cast to fp16
__device__ __half g_Y1[NN * FI];     // Y1 = L x
__device__ __half g_Y2[NN * FI];     // Y2 = L Y1
__device__ __half g_Y3[NN * FI];     // Y3 = L Y2
// B operand [chunk kb][n 0..255][k 0..63] fp16, SW128-pre-swizzled (32KB/chunk)
__device__ __half g_B[4 * 256 * 64];
__device__ float  g_bias[256];       // b_x[g]+b_h[g] for gate0|gate2
__device__ int    g_any;             // detector: any odd word nonzero? (0 => int64)

// ---------------- edge-index access (dtype-robust, trap-proof) -------------
__device__ __forceinline__ int eidx(const void* ei, unsigned i) {
    int v;
    if (g_any == 0) v = (int)((const long long*)ei)[i];   // int64 layout
    else            v = ((const int*)ei)[i];              // int32 layout
    return v & (NN - 1);             // NN = 2^17: no-op for valid ids, trap-proof
}

// ---------------- helpers ----------------------------------------------------
__device__ __forceinline__ uint32_t smem_u32(const void* p) {
    uint32_t a;
    asm("{ .reg .u64 t; cvta.to.shared.u64 t, %1; cvt.u32.u64 %0, t; }"
        : "=r"(a) : "l"(p));
    return a;
}
#define SWZ128(o) ((o) ^ (((o) >> 3) & 0x70))

__device__ __forceinline__ void ldsm4(uint32_t& r0, uint32_t& r1, uint32_t& r2,
                                      uint32_t& r3, uint32_t addr) {
    asm volatile("ldmatrix.sync.aligned.m8n8.x4.shared.b16 {%0,%1,%2,%3}, [%4];"
                 : "=r"(r0), "=r"(r1), "=r"(r2), "=r"(r3) : "r"(addr));
}
__device__ __forceinline__ void mma16816(float* c, const uint32_t* a,
                                         uint32_t b0, uint32_t b1) {
    asm volatile("mma.sync.aligned.m16n8k16.row.col.f32.f16.f16.f32 "
                 "{%0,%1,%2,%3}, {%4,%5,%6,%7}, {%8,%9}, {%0,%1,%2,%3};"
                 : "+f"(c[0]), "+f"(c[1]), "+f"(c[2]), "+f"(c[3])
                 : "r"(a[0]), "r"(a[1]), "r"(a[2]), "r"(a[3]), "r"(b0), "r"(b1));
}
__device__ __forceinline__ void cpa16(uint32_t dst, const void* src) {
    asm volatile("cp.async.cg.shared.global [%0], [%1], 16;"
                 :: "r"(dst), "l"(src));
}
__device__ __forceinline__ float gru_h(float u, float v) {
    float z  = __fdividef(1.f, 1.f + __expf(-u));             // sigmoid
    float th = 1.f - __fdividef(2.f, __expf(2.f * v) + 1.f);  // tanh, inf-safe
    return fmaxf((1.f - z) * th, 0.f);                        // relu((1-z)*tanh)
}

// ---------------- prep kernels ---------------------------------------------
// sample odd 32-bit words of the first 2*NE words: all-zero <=> int64 layout
__global__ void k_detect(const int* __restrict__ w) {
    int t = blockIdx.x * 256 + threadIdx.x;      // 4096 samples
    int stride = (2 * (NE / 4096));
    int v = w[(unsigned)(t * stride + 1)];
    if (__syncthreads_or(v != 0) && threadIdx.x == 0) atomicOr(&g_any, 1);
}

// x -> fp16 cast
__global__ void k_xcast(const float4* __restrict__ x) {
    int i = blockIdx.x * 256 + threadIdx.x;      // NN*FI/4 threads
    float4 v = x[i];
    __half2 a = __floats2half2_rn(v.x, v.y);
    __half2 b = __floats2half2_rn(v.z, v.w);
    uint2 o;
    o.x = *reinterpret_cast<uint32_t*>(&a);
    o.y = *reinterpret_cast<uint32_t*>(&b);
    *reinterpret_cast<uint2*>(g_xh + (size_t)i * 4) = o;
}

// weighted degree (by src) + in-degree histogram (by dst); histogram atomic's
// return value IS the CSR rank -> saved for atomic-free scatter
__global__ void k_deg(const void* __restrict__ ei, const float* __restrict__ ew) {
    unsigned e = blockIdx.x * 256 + threadIdx.x;
    if (e >= NE) return;
    atomicAdd(&g_deg[eidx(ei, e)], ew[e]);
    g_rank[e] = atomicAdd(&g_cnt[eidx(ei, NE + e)], 1);
}

// single-block blocked scan: thread t owns counts [t*128, t*128+128).
// Pass 1: serial totals; block-scan totals; pass 2: write exclusive offsets.
// Fused: dinv on g_deg (same index space).
__global__ void __launch_bounds__(1024) k_scan() {
    __shared__ int wsum[32];
    const int tid  = threadIdx.x;
    const int lane = tid & 31;
    const int w    = tid >> 5;
    const int4* c4 = (const int4*)g_cnt + tid * 32;

    // fused dinv (independent of scan data)
    float4* d4 = (float4*)g_deg + tid * 32;
#pragma unroll 4
    for (int j = 0; j < 32; j++) {
        float4 d = d4[j];
        d.x = (d.x > 0.f) ? rsqrtf(d.x) : 0.f;
        d.y = (d.y > 0.f) ? rsqrtf(d.y) : 0.f;
        d.z = (d.z > 0.f) ? rsqrtf(d.z) : 0.f;
        d.w = (d.w > 0.f) ? rsqrtf(d.w) : 0.f;
        d4[j] = d;
    }

    // pass 1: per-thread total
    int total = 0;
#pragma unroll 4
    for (int j = 0; j < 32; j++) {
        int4 v = c4[j];
        total += v.x + v.y + v.z + v.w;
    }
    // block exclusive scan of 1024 totals
    int x = total;
#pragma unroll
    for (int d = 1; d < 32; d <<= 1) {
        int y = __shfl_up_sync(0xffffffffu, x, d);
        if (lane >= d) x += y;
    }
    if (lane == 31) wsum[w] = x;
    __syncthreads();
    if (w == 0) {
        int s = (lane < 32) ? wsum[lane] : 0;
#pragma unroll
        for (int d = 1; d < 32; d <<= 1) {
            int y = __shfl_up_sync(0xffffffffu, s, d);
            if (lane >= d) s += y;
        }
        wsum[lane] = s;
    }
    __syncthreads();
    int base = x - total + (w > 0 ? wsum[w - 1] : 0);   // exclusive prefix

    // pass 2: write offsets
    int4* o4 = (int4*)g_off + tid * 32;
    int run = base;
#pragma unroll 4
    for (int j = 0; j < 32; j++) {
        int4 v = c4[j];
        int4 o;
        o.x = run;            o.y = run + v.x;
        o.z = o.y + v.y;      o.w = o.z + v.z;
        run = o.w + v.w;
        o4[j] = o;
    }
    if (tid == 1023) g_off[NN] = run;
}

// scatter edges into packed CSR records — NO atomics (rank precomputed)
__global__ void k_scatter(const void* __restrict__ ei, const float* __restrict__ ew) {
    unsigned e = blockIdx.x * 256 + threadIdx.x;
    if (e >= NE) return;
    int s = eidx(ei, e);
    int d = eidx(ei, NE + e);
    float w = -g_deg[s] * ew[e] * g_deg[d];
    unsigned pos = (unsigned)(g_off[d] + g_rank[e]) & (NE - 1);  // trap-proof
    g_edge[pos] = make_int2(s, __float_as_int(w));
}

// Pack B: reparametrized Chebyshev weights (Y_k = L^k x basis), transposed
// [n][k], fp16, SW128-pre-swizzled.
//   B0 = W0 - W2 ; B1 = W1 - 3*W3 ; B2 = 2*W2 ; B3 = 4*W3
__global__ void k_pack(const float* __restrict__ Wx, const float* __restrict__ bx,
                       const float* __restrict__ bh) {
    int i = blockIdx.x * 256 + threadIdx.x;   // 65536 total
    int kb = i >> 14, n = (i >> 6) & 255, kk = i & 63;
    int g  = (n < 128) ? 0 : 2;
    int jj = n & 127;
    const size_t base = (size_t)g * 4 * 64 * 128 + (size_t)kk * 128 + jj;
    const size_t kstep = (size_t)64 * 128;
    float w;
    if      (kb == 0) w = Wx[base]             - Wx[base + 2 * kstep];
    else if (kb == 1) w = Wx[base + kstep]     - 3.f * Wx[base + 3 * kstep];
    else if (kb == 2) w = 2.f * Wx[base + 2 * kstep];
    else              w = 4.f * Wx[base + 3 * kstep];
    uint32_t off = SWZ128((uint32_t)(n * 128 + kk * 2));   // byte off in 32KB tile
    g_B[(uint32_t)kb * 16384 + (off >> 1)] = __float2half(w);
    if (kb == 0 && kk == 0) g_bias[n] = bx[g * 128 + jj] + bh[g * 128 + jj];
}

// ---------------- SpMM gather (fp16 rows): out[d] = sum_e w_e * vin[src_e] --
__global__ void __launch_bounds__(256)
k_spmm(const uint2* __restrict__ vin, uint2* __restrict__ vout) {
    const int node = blockIdx.x * 8 + (threadIdx.x >> 5);
    const int lane = threadIdx.x & 31;
    const int lh   = lane & 15;
    const int half = lane >> 4;
    const int beg = g_off[node];
    const int end = g_off[node + 1];

    float4 acc = make_float4(0.f, 0.f, 0.f, 0.f);
    int i = beg + half;
    for (; i + 2 < end; i += 4) {
        int2 e0 = g_edge[i];
        int2 e1 = g_edge[i + 2];
        uint2 u0 = vin[(long)e0.x * 16 + lh];
        uint2 u1 = vin[(long)e1.x * 16 + lh];
        float w0 = __int_as_float(e0.y);
        float w1 = __int_as_float(e1.y);
        float2 f0 = __half22float2(*reinterpret_cast<__half2*>(&u0.x));
        float2 f1 = __half22float2(*reinterpret_cast<__half2*>(&u0.y));
        float2 f2 = __half22float2(*reinterpret_cast<__half2*>(&u1.x));
        float2 f3 = __half22float2(*reinterpret_cast<__half2*>(&u1.y));
        acc.x = fmaf(w0, f0.x, acc.x); acc.y = fmaf(w0, f0.y, acc.y);
        acc.z = fmaf(w0, f1.x, acc.z); acc.w = fmaf(w0, f1.y, acc.w);
        acc.x = fmaf(w1, f2.x, acc.x); acc.y = fmaf(w1, f2.y, acc.y);
        acc.z = fmaf(w1, f3.x, acc.z); acc.w = fmaf(w1, f3.y, acc.w);
    }
    if (i < end) {
        int2 e0 = g_edge[i];
        uint2 u0 = vin[(long)e0.x * 16 + lh];
        float w0 = __int_as_float(e0.y);
        float2 f0 = __half22float2(*reinterpret_cast<__half2*>(&u0.x));
        float2 f1 = __half22float2(*reinterpret_cast<__half2*>(&u0.y));
        acc.x = fmaf(w0, f0.x, acc.x); acc.y = fmaf(w0, f0.y, acc.y);
        acc.z = fmaf(w0, f1.x, acc.z); acc.w = fmaf(w0, f1.y, acc.w);
    }
    acc.x += __shfl_xor_sync(0xffffffffu, acc.x, 16);
    acc.y += __shfl_xor_sync(0xffffffffu, acc.y, 16);
    acc.z += __shfl_xor_sync(0xffffffffu, acc.z, 16);
    acc.w += __shfl_xor_sync(0xffffffffu, acc.w, 16);

    if (half == 0) {
        __half2 h01 = __floats2half2_rn(acc.x, acc.y);
        __half2 h23 = __floats2half2_rn(acc.z, acc.w);
        uint2 o;
        o.x = *reinterpret_cast<uint32_t*>(&h01);
        o.y = *reinterpret_cast<uint32_t*>(&h23);
        vout[(long)node * 16 + lh] = o;
    }
}

// ---------------- mma.sync GEMM [128 rows/CTA, N=256, K=256] + GRU epilogue -
// A fp16, B fp16; fp32 accum. cp.async double-buffered (round-8 proven config).
// SMEM (dynamic): [0..1024) row-reduce; A ping-pong @1024 (2x16KB);
//                 B ping-pong @33792 (2x32KB). Total 99328 B.
#define SM_A0  1024
#define SM_B0  33792
#define SM_DYN 99328

__global__ void __launch_bounds__(256, 1)
k_gemm_mma(const float* __restrict__ Wlin, const float* __restrict__ blin,
           float* __restrict__ outbuf) {
    extern __shared__ char smem[];
    float* smf = (float*)smem;               // [0..128) rs, [128..256) dt
    const uint32_t sb  = smem_u32(smem);
    const int tid  = threadIdx.x;
    const int wid  = tid >> 5;
    const int lane = tid & 31;
    const int wm   = wid & 3;                // m quarter: rows wm*32..+31
    const int wn   = wid >> 2;               // n half pattern
    const long rowBase = (long)blockIdx.x * 128;

    if (tid < 128) { smf[tid] = 0.f; smf[128 + tid] = 0.f; }

    const __half* bases[4] = { g_xh + rowBase * FI, g_Y1 + rowBase * FI,
                               g_Y2 + rowBase * FI, g_Y3 + rowBase * FI };

    // async stage of chunk c into buffer b (A swizzled on the fly, B pre-swizzled)
    auto stage = [&](int c, int b) {
        const uint4* Asrc = (const uint4*)bases[c];
        uint32_t abase = sb + SM_A0 + (uint32_t)b * 16384;
#pragma unroll
        for (int it = 0; it < 4; it++) {
            int idx = tid + it * 256;           // 1024 uint4
            int r  = idx >> 3;
            int c8 = idx & 7;
            cpa16(abase + (uint32_t)(r * 128 + ((c8 ^ (r & 7)) << 4)), Asrc + idx);
        }
        const uint4* Bsrc = (const uint4*)(g_B + (size_t)c * 16384);
        uint32_t bbase = sb + SM_B0 + (uint32_t)b * 32768;
#pragma unroll
        for (int it = 0; it < 8; it++) {
            int idx = tid + it * 256;           // 2048 uint4
            cpa16(bbase + (uint32_t)idx * 16, Bsrc + idx);
        }
        asm volatile("cp.async.commit_group;");
    };

    float acc[2][16][4];
#pragma unroll
    for (int mt = 0; mt < 2; mt++)
#pragma unroll
        for (int t = 0; t < 16; t++)
#pragma unroll
            for (int q = 0; q < 4; q++) acc[mt][t][q] = 0.f;

    stage(0, 0);

#pragma unroll 1
    for (int c = 0; c < 4; c++) {
        const int cur = c & 1;
        if (c < 3) {
            stage(c + 1, cur ^ 1);
            asm volatile("cp.async.wait_group 1;");
        } else {
            asm volatile("cp.async.wait_group 0;");
        }
        __syncthreads();

        const uint32_t Aoff = SM_A0 + (uint32_t)cur * 16384;
        const uint32_t Boff = SM_B0 + (uint32_t)cur * 32768;
#pragma unroll
        for (int ks = 0; ks < 4; ks++) {
            uint32_t a[2][4];
#pragma unroll
            for (int mt = 0; mt < 2; mt++) {
                int r = wm * 32 + mt * 16 + (lane & 15);
                int g = 2 * ks + (lane >> 4);
                uint32_t ad = sb + Aoff + (uint32_t)(r * 128 + ((g ^ (r & 7)) << 4));
                ldsm4(a[mt][0], a[mt][1], a[mt][2], a[mt][3], ad);
            }
#pragma unroll
            for (int p = 0; p < 8; p++) {
                int tix = (p < 4) ? (2 * p) : (8 + 2 * (p - 4));
                int ntb = wn * 8 + ((p < 4) ? (2 * p) : (16 + 2 * (p - 4)));
                int n = ntb * 8 + (lane & 7) + ((lane >> 4) << 3);
                int g = 2 * ks + ((lane >> 3) & 1);
                uint32_t bd = sb + Boff + (uint32_t)(n * 128 + ((g ^ (n & 7)) << 4));
                uint32_t b0, b1, b2, b3;
                ldsm4(b0, b1, b2, b3, bd);
                mma16816(acc[0][tix],     a[0], b0, b1);
                mma16816(acc[1][tix],     a[1], b0, b1);
                mma16816(acc[0][tix + 1], a[0], b2, b3);
                mma16816(acc[1][tix + 1], a[1], b2, b3);
            }
        }
        __syncthreads();
    }

    // ---- GRU epilogue on register accumulators -----------------------------
    const float bl = __ldg(blin);
#pragma unroll
    for (int mt = 0; mt < 2; mt++) {
        float rs0 = 0.f, dt0 = 0.f, rs1 = 0.f, dt1 = 0.f;
#pragma unroll
        for (int i = 0; i < 8; i++) {
            int j0 = wn * 64 + i * 8 + 2 * (lane & 3);
            float bu0 = __ldg(g_bias + j0),       bu1 = __ldg(g_bias + j0 + 1);
            float bv0 = __ldg(g_bias + j0 + 128), bv1 = __ldg(g_bias + j0 + 129);
            float w0  = __ldg(Wlin + j0),         w1  = __ldg(Wlin + j0 + 1);
            float h00 = gru_h(acc[mt][i][0] + bu0, acc[mt][8 + i][0] + bv0);
            float h01 = gru_h(acc[mt][i][1] + bu1, acc[mt][8 + i][1] + bv1);
            float h10 = gru_h(acc[mt][i][2] + bu0, acc[mt][8 + i][2] + bv0);
            float h11 = gru_h(acc[mt][i][3] + bu1, acc[mt][8 + i][3] + bv1);
            rs0 += h00 + h01; dt0 = fmaf(h00, w0, fmaf(h01, w1, dt0));
            rs1 += h10 + h11; dt1 = fmaf(h10, w0, fmaf(h11, w1, dt1));
        }
#pragma unroll
        for (int s = 1; s < 4; s <<= 1) {
            rs0 += __shfl_xor_sync(0xffffffffu, rs0, s);
            dt0 += __shfl_xor_sync(0xffffffffu, dt0, s);
            rs1 += __shfl_xor_sync(0xffffffffu, rs1, s);
            dt1 += __shfl_xor_sync(0xffffffffu, dt1, s);
        }
        if ((lane & 3) == 0) {
            int r = wm * 32 + mt * 16 + (lane >> 2);
            atomicAdd(&smf[r],           rs0);
            atomicAdd(&smf[128 + r],     dt0);
            atomicAdd(&smf[r + 8],       rs1);
            atomicAdd(&smf[128 + r + 8], dt1);
        }
    }
    __syncthreads();
    if (tid < 128) {
        long grow = rowBase + tid;
        outbuf[grow]      = smf[128 + tid] + bl;   // out = h @ W_lin + b_lin
        outbuf[NN + grow] = sqrtf(smf[tid]);       // logits = sqrt(rowsum(relu(H)))
    }
}

// ---------------- launch orchestration -------------------------------------
extern "C" void kernel_launch(void* const* d_in, const int* in_sizes, int n_in,
                              void* d_out, int out_size) {
    const float* x  = (const float*)d_in[0];
    const void*  ei = d_in[1];                 // int32 or int64 — detected on device
    const float* ew = (const float*)d_in[2];
    const float* Wx = (const float*)d_in[3];
    // d_in[4] = W_h : provably unused (H==0 => cheb(H,*) == bias)
    const float* bx = (const float*)d_in[5];
    const float* bh = (const float*)d_in[6];
    const float* Wl = (const float*)d_in[7];
    const float* bl = (const float*)d_in[8];
    float* out = (float*)d_out;
    (void)in_sizes; (void)n_in; (void)out_size;

    void *pXh, *pY1, *pY2, *pY3, *pdeg, *pcnt, *pany;
    cudaGetSymbolAddress(&pXh, g_xh);
    cudaGetSymbolAddress(&pY1, g_Y1);
    cudaGetSymbolAddress(&pY2, g_Y2);
    cudaGetSymbolAddress(&pY3, g_Y3);
    cudaGetSymbolAddress(&pdeg, g_deg);
    cudaGetSymbolAddress(&pcnt, g_cnt);
    cudaGetSymbolAddress(&pany, g_any);

    cudaFuncSetAttribute(k_gemm_mma, cudaFuncAttributeMaxDynamicSharedMemorySize, SM_DYN);

    // ---- prep
    cudaMemsetAsync(pdeg, 0, (size_t)NN * sizeof(float));
    cudaMemsetAsync(pcnt, 0, (size_t)NN * sizeof(int));
    cudaMemsetAsync(pany, 0, sizeof(int));
    k_detect <<<16, 256>>>((const int*)ei);
    k_xcast  <<<(NN * FI / 4) / 256, 256>>>((const float4*)x);
    k_pack   <<<256, 256>>>(Wx, bx, bh);
    k_deg    <<<NE / 256, 256>>>(ei, ew);
    k_scan   <<<1, 1024>>>();                  // scan + fused dinv
    k_scatter<<<NE / 256, 256>>>(ei, ew);

    // ---- power basis: Y1 = L x ; Y2 = L Y1 ; Y3 = L Y2   (fp16 storage)
    k_spmm<<<NN / 8, 256>>>((const uint2*)pXh, (uint2*)pY1);
    k_spmm<<<NN / 8, 256>>>((const uint2*)pY1, (uint2*)pY2);
    k_spmm<<<NN / 8, 256>>>((const uint2*)pY2, (uint2*)pY3);

    // ---- fused mma.sync GEMM + GRU + head
    k_gemm_mma<<<NN / 128, 256, SM_DYN>>>(Wl, bl, out);
}

// round 11
// speedup vs baseline: 1.0389x; 1.0389x over previous
#include <cuda_runtime.h>
#include <cuda_fp16.h>
#include <cstdint>

#define NN 131072
#define NE 4194304
#define FI 64

// ---------------- scratch (device globals: no allocation allowed) ----------
__device__ float  g_deg [NN];        // raw weighted degree (by src)
__device__ int    g_cnt [NN];        // in-degree histogram (by dst)
__device__ int    g_off [NN + 1];    // CSR row offsets (by dst)
__device__ int    g_cur [NN];        // (written by scan; kept for layout parity)
__device__ int    g_rank[NE];        // per-edge rank within its dst row
__device__ int2   g_edge[NE];        // CSR record: {src, weight-bits}
__device__ __half g_xh[NN * FI];     // x cast to fp16
__device__ __half g_Y1[NN * FI];     // Y1 = L x
__device__ __half g_Y2[NN * FI];     // Y2 = L Y1
__device__ __half g_Y3[NN * FI];     // Y3 = L Y2
// B operand [chunk kb][n 0..255][k 0..63] fp16, SW128-pre-swizzled (32KB/chunk)
__device__ __half g_B[4 * 256 * 64];
__device__ float  g_bias[256];       // b_x[g]+b_h[g] for gate0|gate2
__device__ int    g_any;             // detector: any odd word nonzero?
__device__ int    g_is64;            // 1 if edge_index is int64

// ---------------- edge-index access (dtype-robust, trap-proof) -------------
__device__ __forceinline__ int eidx(const void* ei, unsigned i) {
    int v;
    if (g_is64) v = (int)((const long long*)ei)[i];
    else        v = ((const int*)ei)[i];
    return v & (NN - 1);             // NN = 2^17: no-op for valid ids, trap-proof
}

// ---------------- helpers ----------------------------------------------------
__device__ __forceinline__ uint32_t smem_u32(const void* p) {
    uint32_t a;
    asm("{ .reg .u64 t; cvta.to.shared.u64 t, %1; cvt.u32.u64 %0, t; }"
        : "=r"(a) : "l"(p));
    return a;
}
#define SWZ128(o) ((o) ^ (((o) >> 3) & 0x70))

__device__ __forceinline__ void ldsm4(uint32_t& r0, uint32_t& r1, uint32_t& r2,
                                      uint32_t& r3, uint32_t addr) {
    asm volatile("ldmatrix.sync.aligned.m8n8.x4.shared.b16 {%0,%1,%2,%3}, [%4];"
                 : "=r"(r0), "=r"(r1), "=r"(r2), "=r"(r3) : "r"(addr));
}
__device__ __forceinline__ void mma16816(float* c, const uint32_t* a,
                                         uint32_t b0, uint32_t b1) {
    asm volatile("mma.sync.aligned.m16n8k16.row.col.f32.f16.f16.f32 "
                 "{%0,%1,%2,%3}, {%4,%5,%6,%7}, {%8,%9}, {%0,%1,%2,%3};"
                 : "+f"(c[0]), "+f"(c[1]), "+f"(c[2]), "+f"(c[3])
                 : "r"(a[0]), "r"(a[1]), "r"(a[2]), "r"(a[3]), "r"(b0), "r"(b1));
}
__device__ __forceinline__ void cpa16(uint32_t dst, const void* src) {
    asm volatile("cp.async.cg.shared.global [%0], [%1], 16;"
                 :: "r"(dst), "l"(src));
}
__device__ __forceinline__ float gru_h(float u, float v) {
    float z  = __fdividef(1.f, 1.f + __expf(-u));             // sigmoid
    float th = 1.f - __fdividef(2.f, __expf(2.f * v) + 1.f);  // tanh, inf-safe
    return fmaxf((1.f - z) * th, 0.f);                        // relu((1-z)*tanh)
}

// ---------------- prep kernels ---------------------------------------------
// x -> fp16 cast; blocks 0..15 additionally sample odd 32-bit words of the
// first 2*NE words of edge_index (all-zero <=> int64 layout)
__global__ void k_xcast(const float4* __restrict__ x, const int* __restrict__ w) {
    int i = blockIdx.x * 256 + threadIdx.x;      // NN*FI/4 threads
    float4 v = x[i];
    __half2 a = __floats2half2_rn(v.x, v.y);
    __half2 b = __floats2half2_rn(v.z, v.w);
    uint2 o;
    o.x = *reinterpret_cast<uint32_t*>(&a);
    o.y = *reinterpret_cast<uint32_t*>(&b);
    *reinterpret_cast<uint2*>(g_xh + (size_t)i * 4) = o;

    if (blockIdx.x < 16) {                       // fused dtype detector
        int t = blockIdx.x * 256 + threadIdx.x;  // 4096 samples
        int stride = (2 * (NE / 4096));
        int vv = w[(unsigned)(t * stride + 1)];
        if (__syncthreads_or(vv != 0) && threadIdx.x == 0) atomicOr(&g_any, 1);
    }
}
__global__ void k_setflag() { g_is64 = (g_any == 0); }

// weighted degree (by src) + in-degree histogram (by dst); histogram atomic's
// return value IS the CSR rank -> saved for atomic-free scatter
__global__ void k_deg(const void* __restrict__ ei, const float* __restrict__ ew) {
    unsigned e = blockIdx.x * 256 + threadIdx.x;
    if (e >= NE) return;
    atomicAdd(&g_deg[eidx(ei, e)], ew[e]);
    g_rank[e] = atomicAdd(&g_cnt[eidx(ei, NE + e)], 1);
}

// single-block exclusive scan of g_cnt -> g_off  (1024 threads, distributed)
__global__ void k_scan() {
    __shared__ int wsum[32];
    __shared__ int carry_s;
    const int tid  = threadIdx.x;
    const int lane = tid & 31;
    const int w    = tid >> 5;
    int carry = 0;
    for (int base = 0; base < NN; base += 1024) {
        int v = g_cnt[base + tid];
        int x = v;
#pragma unroll
        for (int d = 1; d < 32; d <<= 1) {
            int y = __shfl_up_sync(0xffffffffu, x, d);
            if (lane >= d) x += y;
        }
        if (lane == 31) wsum[w] = x;
        __syncthreads();
        if (w == 0) {
            int s = wsum[lane];
#pragma unroll
            for (int d = 1; d < 32; d <<= 1) {
                int y = __shfl_up_sync(0xffffffffu, s, d);
                if (lane >= d) s += y;
            }
            wsum[lane] = s;
        }
        __syncthreads();
        int incl = x + (w > 0 ? wsum[w - 1] : 0) + carry;
        g_off[base + tid] = incl - v;
        if (tid == 1023) carry_s = incl;
        __syncthreads();
        carry = carry_s;
        __syncthreads();
    }
    if (tid == 0) g_off[NN] = carry;
}

// scatter edges into packed CSR records — NO atomics (rank precomputed);
// dinv fused: rsqrt applied to raw degrees inline (MUFU hidden under memory)
__global__ void k_scatter(const void* __restrict__ ei, const float* __restrict__ ew) {
    unsigned e = blockIdx.x * 256 + threadIdx.x;
    if (e >= NE) return;
    int s = eidx(ei, e);
    int d = eidx(ei, NE + e);
    float ds = g_deg[s], dd = g_deg[d];
    float is = (ds > 0.f) ? rsqrtf(ds) : 0.f;
    float id = (dd > 0.f) ? rsqrtf(dd) : 0.f;
    float w = -is * ew[e] * id;
    unsigned pos = (unsigned)(g_off[d] + g_rank[e]) & (NE - 1);  // trap-proof
    g_edge[pos] = make_int2(s, __float_as_int(w));
}

// Pack B: reparametrized Chebyshev weights (Y_k = L^k x basis), transposed
// [n][k], fp16, SW128-pre-swizzled.
//   B0 = W0 - W2 ; B1 = W1 - 3*W3 ; B2 = 2*W2 ; B3 = 4*W3
__global__ void k_pack(const float* __restrict__ Wx, const float* __restrict__ bx,
                       const float* __restrict__ bh) {
    int i = blockIdx.x * 256 + threadIdx.x;   // 65536 total
    int kb = i >> 14, n = (i >> 6) & 255, kk = i & 63;
    int g  = (n < 128) ? 0 : 2;
    int jj = n & 127;
    const size_t base = (size_t)g * 4 * 64 * 128 + (size_t)kk * 128 + jj;
    const size_t kstep = (size_t)64 * 128;
    float w;
    if      (kb == 0) w = Wx[base]             - Wx[base + 2 * kstep];
    else if (kb == 1) w = Wx[base + kstep]     - 3.f * Wx[base + 3 * kstep];
    else if (kb == 2) w = 2.f * Wx[base + 2 * kstep];
    else              w = 4.f * Wx[base + 3 * kstep];
    uint32_t off = SWZ128((uint32_t)(n * 128 + kk * 2));   // byte off in 32KB tile
    g_B[(uint32_t)kb * 16384 + (off >> 1)] = __float2half(w);
    if (kb == 0 && kk == 0) g_bias[n] = bx[g * 128 + jj] + bh[g * 128 + jj];
}

// ---------------- SpMM gather (fp16 rows): out[d] = sum_e w_e * vin[src_e] --
__global__ void __launch_bounds__(256)
k_spmm(const uint2* __restrict__ vin, uint2* __restrict__ vout) {
    const int node = blockIdx.x * 8 + (threadIdx.x >> 5);
    const int lane = threadIdx.x & 31;
    const int lh   = lane & 15;
    const int half = lane >> 4;
    const int beg = g_off[node];
    const int end = g_off[node + 1];

    float4 acc = make_float4(0.f, 0.f, 0.f, 0.f);
    int i = beg + half;
    for (; i + 2 < end; i += 4) {
        int2 e0 = g_edge[i];
        int2 e1 = g_edge[i + 2];
        uint2 u0 = vin[(long)e0.x * 16 + lh];
        uint2 u1 = vin[(long)e1.x * 16 + lh];
        float w0 = __int_as_float(e0.y);
        float w1 = __int_as_float(e1.y);
        float2 f0 = __half22float2(*reinterpret_cast<__half2*>(&u0.x));
        float2 f1 = __half22float2(*reinterpret_cast<__half2*>(&u0.y));
        float2 f2 = __half22float2(*reinterpret_cast<__half2*>(&u1.x));
        float2 f3 = __half22float2(*reinterpret_cast<__half2*>(&u1.y));
        acc.x = fmaf(w0, f0.x, acc.x); acc.y = fmaf(w0, f0.y, acc.y);
        acc.z = fmaf(w0, f1.x, acc.z); acc.w = fmaf(w0, f1.y, acc.w);
        acc.x = fmaf(w1, f2.x, acc.x); acc.y = fmaf(w1, f2.y, acc.y);
        acc.z = fmaf(w1, f3.x, acc.z); acc.w = fmaf(w1, f3.y, acc.w);
    }
    if (i < end) {
        int2 e0 = g_edge[i];
        uint2 u0 = vin[(long)e0.x * 16 + lh];
        float w0 = __int_as_float(e0.y);
        float2 f0 = __half22float2(*reinterpret_cast<__half2*>(&u0.x));
        float2 f1 = __half22float2(*reinterpret_cast<__half2*>(&u0.y));
        acc.x = fmaf(w0, f0.x, acc.x); acc.y = fmaf(w0, f0.y, acc.y);
        acc.z = fmaf(w0, f1.x, acc.z); acc.w = fmaf(w0, f1.y, acc.w);
    }
    acc.x += __shfl_xor_sync(0xffffffffu, acc.x, 16);
    acc.y += __shfl_xor_sync(0xffffffffu, acc.y, 16);
    acc.z += __shfl_xor_sync(0xffffffffu, acc.z, 16);
    acc.w += __shfl_xor_sync(0xffffffffu, acc.w, 16);

    if (half == 0) {
        __half2 h01 = __floats2half2_rn(acc.x, acc.y);
        __half2 h23 = __floats2half2_rn(acc.z, acc.w);
        uint2 o;
        o.x = *reinterpret_cast<uint32_t*>(&h01);
        o.y = *reinterpret_cast<uint32_t*>(&h23);
        vout[(long)node * 16 + lh] = o;
    }
}

// ---------------- mma.sync GEMM [128 rows/CTA, N=256, K=256] + GRU epilogue -
// A fp16, B fp16; fp32 accum. cp.async double-buffered (round-8 proven config).
// SMEM (dynamic): [0..1024) row-reduce; A ping-pong @1024 (2x16KB);
//                 B ping-pong @33792 (2x32KB). Total 99328 B.
#define SM_A0  1024
#define SM_B0  33792
#define SM_DYN 99328

__global__ void __launch_bounds__(256, 1)
k_gemm_mma(const float* __restrict__ Wlin, const float* __restrict__ blin,
           float* __restrict__ outbuf) {
    extern __shared__ char smem[];
    float* smf = (float*)smem;               // [0..128) rs, [128..256) dt
    const uint32_t sb  = smem_u32(smem);
    const int tid  = threadIdx.x;
    const int wid  = tid >> 5;
    const int lane = tid & 31;
    const int wm   = wid & 3;                // m quarter: rows wm*32..+31
    const int wn   = wid >> 2;               // n half pattern
    const long rowBase = (long)blockIdx.x * 128;

    if (tid < 128) { smf[tid] = 0.f; smf[128 + tid] = 0.f; }

    const __half* bases[4] = { g_xh + rowBase * FI, g_Y1 + rowBase * FI,
                               g_Y2 + rowBase * FI, g_Y3 + rowBase * FI };

    // async stage of chunk c into buffer b (A swizzled on the fly, B pre-swizzled)
    auto stage = [&](int c, int b) {
        const uint4* Asrc = (const uint4*)bases[c];
        uint32_t abase = sb + SM_A0 + (uint32_t)b * 16384;
#pragma unroll
        for (int it = 0; it < 4; it++) {
            int idx = tid + it * 256;           // 1024 uint4
            int r  = idx >> 3;
            int c8 = idx & 7;
            cpa16(abase + (uint32_t)(r * 128 + ((c8 ^ (r & 7)) << 4)), Asrc + idx);
        }
        const uint4* Bsrc = (const uint4*)(g_B + (size_t)c * 16384);
        uint32_t bbase = sb + SM_B0 + (uint32_t)b * 32768;
#pragma unroll
        for (int it = 0; it < 8; it++) {
            int idx = tid + it * 256;           // 2048 uint4
            cpa16(bbase + (uint32_t)idx * 16, Bsrc + idx);
        }
        asm volatile("cp.async.commit_group;");
    };

    float acc[2][16][4];
#pragma unroll
    for (int mt = 0; mt < 2; mt++)
#pragma unroll
        for (int t = 0; t < 16; t++)
#pragma unroll
            for (int q = 0; q < 4; q++) acc[mt][t][q] = 0.f;

    stage(0, 0);

#pragma unroll 1
    for (int c = 0; c < 4; c++) {
        const int cur = c & 1;
        if (c < 3) {
            stage(c + 1, cur ^ 1);
            asm volatile("cp.async.wait_group 1;");
        } else {
            asm volatile("cp.async.wait_group 0;");
        }
        __syncthreads();

        const uint32_t Aoff = SM_A0 + (uint32_t)cur * 16384;
        const uint32_t Boff = SM_B0 + (uint32_t)cur * 32768;
#pragma unroll
        for (int ks = 0; ks < 4; ks++) {
            uint32_t a[2][4];
#pragma unroll
            for (int mt = 0; mt < 2; mt++) {
                int r = wm * 32 + mt * 16 + (lane & 15);
                int g = 2 * ks + (lane >> 4);
                uint32_t ad = sb + Aoff + (uint32_t)(r * 128 + ((g ^ (r & 7)) << 4));
                ldsm4(a[mt][0], a[mt][1], a[mt][2], a[mt][3], ad);
            }
#pragma unroll
            for (int p = 0; p < 8; p++) {
                int tix = (p < 4) ? (2 * p) : (8 + 2 * (p - 4));
                int ntb = wn * 8 + ((p < 4) ? (2 * p) : (16 + 2 * (p - 4)));
                int n = ntb * 8 + (lane & 7) + ((lane >> 4) << 3);
                int g = 2 * ks + ((lane >> 3) & 1);
                uint32_t bd = sb + Boff + (uint32_t)(n * 128 + ((g ^ (n & 7)) << 4));
                uint32_t b0, b1, b2, b3;
                ldsm4(b0, b1, b2, b3, bd);
                mma16816(acc[0][tix],     a[0], b0, b1);
                mma16816(acc[1][tix],     a[1], b0, b1);
                mma16816(acc[0][tix + 1], a[0], b2, b3);
                mma16816(acc[1][tix + 1], a[1], b2, b3);
            }
        }
        __syncthreads();
    }

    // ---- GRU epilogue on register accumulators -----------------------------
    const float bl = __ldg(blin);
#pragma unroll
    for (int mt = 0; mt < 2; mt++) {
        float rs0 = 0.f, dt0 = 0.f, rs1 = 0.f, dt1 = 0.f;
#pragma unroll
        for (int i = 0; i < 8; i++) {
            int j0 = wn * 64 + i * 8 + 2 * (lane & 3);
            float bu0 = __ldg(g_bias + j0),       bu1 = __ldg(g_bias + j0 + 1);
            float bv0 = __ldg(g_bias + j0 + 128), bv1 = __ldg(g_bias + j0 + 129);
            float w0  = __ldg(Wlin + j0),         w1  = __ldg(Wlin + j0 + 1);
            float h00 = gru_h(acc[mt][i][0] + bu0, acc[mt][8 + i][0] + bv0);
            float h01 = gru_h(acc[mt][i][1] + bu1, acc[mt][8 + i][1] + bv1);
            float h10 = gru_h(acc[mt][i][2] + bu0, acc[mt][8 + i][2] + bv0);
            float h11 = gru_h(acc[mt][i][3] + bu1, acc[mt][8 + i][3] + bv1);
            rs0 += h00 + h01; dt0 = fmaf(h00, w0, fmaf(h01, w1, dt0));
            rs1 += h10 + h11; dt1 = fmaf(h10, w0, fmaf(h11, w1, dt1));
        }
#pragma unroll
        for (int s = 1; s < 4; s <<= 1) {
            rs0 += __shfl_xor_sync(0xffffffffu, rs0, s);
            dt0 += __shfl_xor_sync(0xffffffffu, dt0, s);
            rs1 += __shfl_xor_sync(0xffffffffu, rs1, s);
            dt1 += __shfl_xor_sync(0xffffffffu, dt1, s);
        }
        if ((lane & 3) == 0) {
            int r = wm * 32 + mt * 16 + (lane >> 2);
            atomicAdd(&smf[r],           rs0);
            atomicAdd(&smf[128 + r],     dt0);
            atomicAdd(&smf[r + 8],       rs1);
            atomicAdd(&smf[128 + r + 8], dt1);
        }
    }
    __syncthreads();
    if (tid < 128) {
        long grow = rowBase + tid;
        outbuf[grow]      = smf[128 + tid] + bl;   // out = h @ W_lin + b_lin
        outbuf[NN + grow] = sqrtf(smf[tid]);       // logits = sqrt(rowsum(relu(H)))
    }
}

// ---------------- launch orchestration -------------------------------------
extern "C" void kernel_launch(void* const* d_in, const int* in_sizes, int n_in,
                              void* d_out, int out_size) {
    const float* x  = (const float*)d_in[0];
    const void*  ei = d_in[1];                 // int32 or int64 — detected on device
    const float* ew = (const float*)d_in[2];
    const float* Wx = (const float*)d_in[3];
    // d_in[4] = W_h : provably unused (H==0 => cheb(H,*) == bias)
    const float* bx = (const float*)d_in[5];
    const float* bh = (const float*)d_in[6];
    const float* Wl = (const float*)d_in[7];
    const float* bl = (const float*)d_in[8];
    float* out = (float*)d_out;
    (void)in_sizes; (void)n_in; (void)out_size;

    void *pXh, *pY1, *pY2, *pY3, *pdeg, *pcnt, *pany;
    cudaGetSymbolAddress(&pXh, g_xh);
    cudaGetSymbolAddress(&pY1, g_Y1);
    cudaGetSymbolAddress(&pY2, g_Y2);
    cudaGetSymbolAddress(&pY3, g_Y3);
    cudaGetSymbolAddress(&pdeg, g_deg);
    cudaGetSymbolAddress(&pcnt, g_cnt);
    cudaGetSymbolAddress(&pany, g_any);

    cudaFuncSetAttribute(k_gemm_mma, cudaFuncAttributeMaxDynamicSharedMemorySize, SM_DYN);

    // ---- prep: xcast(+detect) -> setflag -> pack -> deg -> scan -> scatter
    cudaMemsetAsync(pdeg, 0, (size_t)NN * sizeof(float));
    cudaMemsetAsync(pcnt, 0, (size_t)NN * sizeof(int));
    cudaMemsetAsync(pany, 0, sizeof(int));
    k_xcast  <<<(NN * FI / 4) / 256, 256>>>((const float4*)x, (const int*)ei);
    k_setflag<<<1, 1>>>();
    k_pack   <<<256, 256>>>(Wx, bx, bh);
    k_deg    <<<NE / 256, 256>>>(ei, ew);
    k_scan   <<<1, 1024>>>();
    k_scatter<<<NE / 256, 256>>>(ei, ew);   // dinv fused (rsqrt inline)

    // ---- power basis: Y1 = L x ; Y2 = L Y1 ; Y3 = L Y2   (fp16 storage)
    k_spmm<<<NN / 8, 256>>>((const uint2*)pXh, (uint2*)pY1);
    k_spmm<<<NN / 8, 256>>>((const uint2*)pY1, (uint2*)pY2);
    k_spmm<<<NN / 8, 256>>>((const uint2*)pY2, (uint2*)pY3);

    // ---- fused mma.sync GEMM + GRU + head
    k_gemm_mma<<<NN / 128, 256, SM_DYN>>>(Wl, bl, out);
}

// round 12
// speedup vs baseline: 1.0517x; 1.0123x over previous
#include <cuda_runtime.h>
#include <cuda_fp16.h>
#include <cstdint>

#define NN 131072
#define NE 4194304
#define FI 64

// ---------------- scratch (device globals: no allocation allowed) ----------
__device__ float  g_deg [NN];        // raw weighted degree (by src)
__device__ int    g_cnt [NN];        // in-degree histogram (by dst)
__device__ int    g_off [NN + 1];    // CSR row offsets (by dst)
__device__ int    g_rank[NE];        // per-edge rank within its dst row
__device__ int2   g_edge[NE];        // CSR record: {src, weight-bits}
__device__ __half g_xh[NN * FI];     // x cast to fp16
__device__ __half g_Y1[NN * FI];     // Y1 = L x
__device__ __half g_Y2[NN * FI];     // Y2 = L Y1
__device__ __half g_Y3[NN * FI];     // Y3 = L Y2
// B operand [chunk kb][n 0..255][k 0..63] fp16, SW128-pre-swizzled (32KB/chunk)
__device__ __half g_B[4 * 256 * 64];
__device__ float  g_bias[256];       // b_x[g]+b_h[g] for gate0|gate2
__device__ int    g_any;             // detector: any odd word nonzero?
__device__ int    g_is64;            // 1 if edge_index is int64

// ---------------- edge-index access (dtype-robust, trap-proof) -------------
__device__ __forceinline__ int eidx(const void* ei, unsigned i) {
    int v;
    if (g_is64) v = (int)((const long long*)ei)[i];
    else        v = ((const int*)ei)[i];
    return v & (NN - 1);             // NN = 2^17: no-op for valid ids, trap-proof
}

// ---------------- helpers ----------------------------------------------------
__device__ __forceinline__ uint32_t smem_u32(const void* p) {
    uint32_t a;
    asm("{ .reg .u64 t; cvta.to.shared.u64 t, %1; cvt.u32.u64 %0, t; }"
        : "=r"(a) : "l"(p));
    return a;
}
#define SWZ128(o) ((o) ^ (((o) >> 3) & 0x70))

__device__ __forceinline__ void ldsm4(uint32_t& r0, uint32_t& r1, uint32_t& r2,
                                      uint32_t& r3, uint32_t addr) {
    asm volatile("ldmatrix.sync.aligned.m8n8.x4.shared.b16 {%0,%1,%2,%3}, [%4];"
                 : "=r"(r0), "=r"(r1), "=r"(r2), "=r"(r3) : "r"(addr));
}
__device__ __forceinline__ void mma16816(float* c, const uint32_t* a,
                                         uint32_t b0, uint32_t b1) {
    asm volatile("mma.sync.aligned.m16n8k16.row.col.f32.f16.f16.f32 "
                 "{%0,%1,%2,%3}, {%4,%5,%6,%7}, {%8,%9}, {%0,%1,%2,%3};"
                 : "+f"(c[0]), "+f"(c[1]), "+f"(c[2]), "+f"(c[3])
                 : "r"(a[0]), "r"(a[1]), "r"(a[2]), "r"(a[3]), "r"(b0), "r"(b1));
}
__device__ __forceinline__ void cpa16(uint32_t dst, const void* src) {
    asm volatile("cp.async.cg.shared.global [%0], [%1], 16;"
                 :: "r"(dst), "l"(src));
}
__device__ __forceinline__ float gru_h(float u, float v) {
    float z  = __fdividef(1.f, 1.f + __expf(-u));             // sigmoid
    float th = 1.f - __fdividef(2.f, __expf(2.f * v) + 1.f);  // tanh, inf-safe
    return fmaxf((1.f - z) * th, 0.f);                        // relu((1-z)*tanh)
}
__device__ __forceinline__ void acc_edge(float4& acc, int2 e,
                                         const uint2* __restrict__ vin, int lh) {
    uint2 u = vin[(long)e.x * 16 + lh];
    float w = __int_as_float(e.y);
    float2 f0 = __half22float2(*reinterpret_cast<__half2*>(&u.x));
    float2 f1 = __half22float2(*reinterpret_cast<__half2*>(&u.y));
    acc.x = fmaf(w, f0.x, acc.x); acc.y = fmaf(w, f0.y, acc.y);
    acc.z = fmaf(w, f1.x, acc.z); acc.w = fmaf(w, f1.y, acc.w);
}

// ---------------- prep kernels ---------------------------------------------
// x -> fp16 cast; blocks 0..15 additionally sample odd 32-bit words of the
// first 2*NE words of edge_index (all-zero <=> int64 layout)
__global__ void k_xcast(const float4* __restrict__ x, const int* __restrict__ w) {
    int i = blockIdx.x * 256 + threadIdx.x;      // NN*FI/4 threads
    float4 v = x[i];
    __half2 a = __floats2half2_rn(v.x, v.y);
    __half2 b = __floats2half2_rn(v.z, v.w);
    uint2 o;
    o.x = *reinterpret_cast<uint32_t*>(&a);
    o.y = *reinterpret_cast<uint32_t*>(&b);
    *reinterpret_cast<uint2*>(g_xh + (size_t)i * 4) = o;

    if (blockIdx.x < 16) {                       // fused dtype detector
        int t = blockIdx.x * 256 + threadIdx.x;  // 4096 samples
        int stride = (2 * (NE / 4096));
        int vv = w[(unsigned)(t * stride + 1)];
        if (__syncthreads_or(vv != 0) && threadIdx.x == 0) atomicOr(&g_any, 1);
    }
}
__global__ void k_setflag() { g_is64 = (g_any == 0); }

// weighted degree (by src) + in-degree histogram (by dst); histogram atomic's
// return value IS the CSR rank. 2 edges per thread, vectorized loads.
__global__ void k_deg(const void* __restrict__ ei, const float2* __restrict__ ew2) {
    unsigned t = blockIdx.x * 256 + threadIdx.x;     // NE/2 threads
    unsigned e = t * 2;
    int s0, s1, d0, d1;
    if (g_is64) {
        const longlong2* p = (const longlong2*)ei;
        longlong2 sv = p[t];
        longlong2 dv = p[(NE / 2) + t];
        s0 = (int)sv.x & (NN - 1); s1 = (int)sv.y & (NN - 1);
        d0 = (int)dv.x & (NN - 1); d1 = (int)dv.y & (NN - 1);
    } else {
        const int2* p = (const int2*)ei;
        int2 sv = p[t];
        int2 dv = p[(NE / 2) + t];
        s0 = sv.x & (NN - 1); s1 = sv.y & (NN - 1);
        d0 = dv.x & (NN - 1); d1 = dv.y & (NN - 1);
    }
    float2 w = ew2[t];
    atomicAdd(&g_deg[s0], w.x);
    atomicAdd(&g_deg[s1], w.y);
    g_rank[e]     = atomicAdd(&g_cnt[d0], 1);
    g_rank[e + 1] = atomicAdd(&g_cnt[d1], 1);
}

// single-block exclusive scan of g_cnt -> g_off  (1024 threads, distributed)
__global__ void k_scan() {
    __shared__ int wsum[32];
    __shared__ int carry_s;
    const int tid  = threadIdx.x;
    const int lane = tid & 31;
    const int w    = tid >> 5;
    int carry = 0;
    for (int base = 0; base < NN; base += 1024) {
        int v = g_cnt[base + tid];
        int x = v;
#pragma unroll
        for (int d = 1; d < 32; d <<= 1) {
            int y = __shfl_up_sync(0xffffffffu, x, d);
            if (lane >= d) x += y;
        }
        if (lane == 31) wsum[w] = x;
        __syncthreads();
        if (w == 0) {
            int s = wsum[lane];
#pragma unroll
            for (int d = 1; d < 32; d <<= 1) {
                int y = __shfl_up_sync(0xffffffffu, s, d);
                if (lane >= d) s += y;
            }
            wsum[lane] = s;
        }
        __syncthreads();
        int incl = x + (w > 0 ? wsum[w - 1] : 0) + carry;
        g_off[base + tid] = incl - v;
        if (tid == 1023) carry_s = incl;
        __syncthreads();
        carry = carry_s;
        __syncthreads();
    }
    if (tid == 0) g_off[NN] = carry;
}

// scatter edges into packed CSR records — NO atomics (rank precomputed);
// dinv fused: rsqrt applied to raw degrees inline (MUFU hidden under memory)
__global__ void k_scatter(const void* __restrict__ ei, const float* __restrict__ ew) {
    unsigned e = blockIdx.x * 256 + threadIdx.x;
    if (e >= NE) return;
    int s = eidx(ei, e);
    int d = eidx(ei, NE + e);
    float ds = g_deg[s], dd = g_deg[d];
    float is = (ds > 0.f) ? rsqrtf(ds) : 0.f;
    float id = (dd > 0.f) ? rsqrtf(dd) : 0.f;
    float w = -is * ew[e] * id;
    unsigned pos = (unsigned)(g_off[d] + g_rank[e]) & (NE - 1);  // trap-proof
    g_edge[pos] = make_int2(s, __float_as_int(w));
}

// Pack B: reparametrized Chebyshev weights (Y_k = L^k x basis), transposed
// [n][k], fp16, SW128-pre-swizzled.
//   B0 = W0 - W2 ; B1 = W1 - 3*W3 ; B2 = 2*W2 ; B3 = 4*W3
__global__ void k_pack(const float* __restrict__ Wx, const float* __restrict__ bx,
                       const float* __restrict__ bh) {
    int i = blockIdx.x * 256 + threadIdx.x;   // 65536 total
    int kb = i >> 14, n = (i >> 6) & 255, kk = i & 63;
    int g  = (n < 128) ? 0 : 2;
    int jj = n & 127;
    const size_t base = (size_t)g * 4 * 64 * 128 + (size_t)kk * 128 + jj;
    const size_t kstep = (size_t)64 * 128;
    float w;
    if      (kb == 0) w = Wx[base]             - Wx[base + 2 * kstep];
    else if (kb == 1) w = Wx[base + kstep]     - 3.f * Wx[base + 3 * kstep];
    else if (kb == 2) w = 2.f * Wx[base + 2 * kstep];
    else              w = 4.f * Wx[base + 3 * kstep];
    uint32_t off = SWZ128((uint32_t)(n * 128 + kk * 2));   // byte off in 32KB tile
    g_B[(uint32_t)kb * 16384 + (off >> 1)] = __float2half(w);
    if (kb == 0 && kk == 0) g_bias[n] = bx[g * 128 + jj] + bh[g * 128 + jj];
}

// ---------------- SpMM gather (fp16 rows): out[d] = sum_e w_e * vin[src_e] --
// One warp per dst node; 2 half-warps × unroll-4 = 8 edges in flight per warp.
__global__ void __launch_bounds__(256)
k_spmm(const uint2* __restrict__ vin, uint2* __restrict__ vout) {
    const int node = blockIdx.x * 8 + (threadIdx.x >> 5);
    const int lane = threadIdx.x & 31;
    const int lh   = lane & 15;
    const int half = lane >> 4;
    const int beg = g_off[node];
    const int end = g_off[node + 1];

    float4 acc = make_float4(0.f, 0.f, 0.f, 0.f);
    int i = beg + half;
    for (; i + 6 < end; i += 8) {        // 4 edges per half-warp in flight
        int2 e0 = g_edge[i];
        int2 e1 = g_edge[i + 2];
        int2 e2 = g_edge[i + 4];
        int2 e3 = g_edge[i + 6];
        acc_edge(acc, e0, vin, lh);
        acc_edge(acc, e1, vin, lh);
        acc_edge(acc, e2, vin, lh);
        acc_edge(acc, e3, vin, lh);
    }
    for (; i < end; i += 2) {
        int2 e0 = g_edge[i];
        acc_edge(acc, e0, vin, lh);
    }
    acc.x += __shfl_xor_sync(0xffffffffu, acc.x, 16);
    acc.y += __shfl_xor_sync(0xffffffffu, acc.y, 16);
    acc.z += __shfl_xor_sync(0xffffffffu, acc.z, 16);
    acc.w += __shfl_xor_sync(0xffffffffu, acc.w, 16);

    if (half == 0) {
        __half2 h01 = __floats2half2_rn(acc.x, acc.y);
        __half2 h23 = __floats2half2_rn(acc.z, acc.w);
        uint2 o;
        o.x = *reinterpret_cast<uint32_t*>(&h01);
        o.y = *reinterpret_cast<uint32_t*>(&h23);
        vout[(long)node * 16 + lh] = o;
    }
}

// ---------------- mma.sync GEMM [128 rows/CTA, N=256, K=256] + GRU epilogue -
// A fp16, B fp16; fp32 accum. cp.async double-buffered (round-8 proven config).
// SMEM (dynamic): [0..1024) row-reduce; A ping-pong @1024 (2x16KB);
//                 B ping-pong @33792 (2x32KB). Total 99328 B.
#define SM_A0  1024
#define SM_B0  33792
#define SM_DYN 99328

__global__ void __launch_bounds__(256, 1)
k_gemm_mma(const float* __restrict__ Wlin, const float* __restrict__ blin,
           float* __restrict__ outbuf) {
    extern __shared__ char smem[];
    float* smf = (float*)smem;               // [0..128) rs, [128..256) dt
    const uint32_t sb  = smem_u32(smem);
    const int tid  = threadIdx.x;
    const int wid  = tid >> 5;
    const int lane = tid & 31;
    const int wm   = wid & 3;                // m quarter: rows wm*32..+31
    const int wn   = wid >> 2;               // n half pattern
    const long rowBase = (long)blockIdx.x * 128;

    if (tid < 128) { smf[tid] = 0.f; smf[128 + tid] = 0.f; }

    const __half* bases[4] = { g_xh + rowBase * FI, g_Y1 + rowBase * FI,
                               g_Y2 + rowBase * FI, g_Y3 + rowBase * FI };

    // async stage of chunk c into buffer b (A swizzled on the fly, B pre-swizzled)
    auto stage = [&](int c, int b) {
        const uint4* Asrc = (const uint4*)bases[c];
        uint32_t abase = sb + SM_A0 + (uint32_t)b * 16384;
#pragma unroll
        for (int it = 0; it < 4; it++) {
            int idx = tid + it * 256;           // 1024 uint4
            int r  = idx >> 3;
            int c8 = idx & 7;
            cpa16(abase + (uint32_t)(r * 128 + ((c8 ^ (r & 7)) << 4)), Asrc + idx);
        }
        const uint4* Bsrc = (const uint4*)(g_B + (size_t)c * 16384);
        uint32_t bbase = sb + SM_B0 + (uint32_t)b * 32768;
#pragma unroll
        for (int it = 0; it < 8; it++) {
            int idx = tid + it * 256;           // 2048 uint4
            cpa16(bbase + (uint32_t)idx * 16, Bsrc + idx);
        }
        asm volatile("cp.async.commit_group;");
    };

    float acc[2][16][4];
#pragma unroll
    for (int mt = 0; mt < 2; mt++)
#pragma unroll
        for (int t = 0; t < 16; t++)
#pragma unroll
            for (int q = 0; q < 4; q++) acc[mt][t][q] = 0.f;

    stage(0, 0);

#pragma unroll 1
    for (int c = 0; c < 4; c++) {
        const int cur = c & 1;
        if (c < 3) {
            stage(c + 1, cur ^ 1);
            asm volatile("cp.async.wait_group 1;");
        } else {
            asm volatile("cp.async.wait_group 0;");
        }
        __syncthreads();

        const uint32_t Aoff = SM_A0 + (uint32_t)cur * 16384;
        const uint32_t Boff = SM_B0 + (uint32_t)cur * 32768;
#pragma unroll
        for (int ks = 0; ks < 4; ks++) {
            uint32_t a[2][4];
#pragma unroll
            for (int mt = 0; mt < 2; mt++) {
                int r = wm * 32 + mt * 16 + (lane & 15);
                int g = 2 * ks + (lane >> 4);
                uint32_t ad = sb + Aoff + (uint32_t)(r * 128 + ((g ^ (r & 7)) << 4));
                ldsm4(a[mt][0], a[mt][1], a[mt][2], a[mt][3], ad);
            }
#pragma unroll
            for (int p = 0; p < 8; p++) {
                int tix = (p < 4) ? (2 * p) : (8 + 2 * (p - 4));
                int ntb = wn * 8 + ((p < 4) ? (2 * p) : (16 + 2 * (p - 4)));
                int n = ntb * 8 + (lane & 7) + ((lane >> 4) << 3);
                int g = 2 * ks + ((lane >> 3) & 1);
                uint32_t bd = sb + Boff + (uint32_t)(n * 128 + ((g ^ (n & 7)) << 4));
                uint32_t b0, b1, b2, b3;
                ldsm4(b0, b1, b2, b3, bd);
                mma16816(acc[0][tix],     a[0], b0, b1);
                mma16816(acc[1][tix],     a[1], b0, b1);
                mma16816(acc[0][tix + 1], a[0], b2, b3);
                mma16816(acc[1][tix + 1], a[1], b2, b3);
            }
        }
        __syncthreads();
    }

    // ---- GRU epilogue on register accumulators -----------------------------
    const float bl = __ldg(blin);
#pragma unroll
    for (int mt = 0; mt < 2; mt++) {
        float rs0 = 0.f, dt0 = 0.f, rs1 = 0.f, dt1 = 0.f;
#pragma unroll
        for (int i = 0; i < 8; i++) {
            int j0 = wn * 64 + i * 8 + 2 * (lane & 3);
            float bu0 = __ldg(g_bias + j0),       bu1 = __ldg(g_bias + j0 + 1);
            float bv0 = __ldg(g_bias + j0 + 128), bv1 = __ldg(g_bias + j0 + 129);
            float w0  = __ldg(Wlin + j0),         w1  = __ldg(Wlin + j0 + 1);
            float h00 = gru_h(acc[mt][i][0] + bu0, acc[mt][8 + i][0] + bv0);
            float h01 = gru_h(acc[mt][i][1] + bu1, acc[mt][8 + i][1] + bv1);
            float h10 = gru_h(acc[mt][i][2] + bu0, acc[mt][8 + i][2] + bv0);
            float h11 = gru_h(acc[mt][i][3] + bu1, acc[mt][8 + i][3] + bv1);
            rs0 += h00 + h01; dt0 = fmaf(h00, w0, fmaf(h01, w1, dt0));
            rs1 += h10 + h11; dt1 = fmaf(h10, w0, fmaf(h11, w1, dt1));
        }
#pragma unroll
        for (int s = 1; s < 4; s <<= 1) {
            rs0 += __shfl_xor_sync(0xffffffffu, rs0, s);
            dt0 += __shfl_xor_sync(0xffffffffu, dt0, s);
            rs1 += __shfl_xor_sync(0xffffffffu, rs1, s);
            dt1 += __shfl_xor_sync(0xffffffffu, dt1, s);
        }
        if ((lane & 3) == 0) {
            int r = wm * 32 + mt * 16 + (lane >> 2);
            atomicAdd(&smf[r],           rs0);
            atomicAdd(&smf[128 + r],     dt0);
            atomicAdd(&smf[r + 8],       rs1);
            atomicAdd(&smf[128 + r + 8], dt1);
        }
    }
    __syncthreads();
    if (tid < 128) {
        long grow = rowBase + tid;
        outbuf[grow]      = smf[128 + tid] + bl;   // out = h @ W_lin + b_lin
        outbuf[NN + grow] = sqrtf(smf[tid]);       // logits = sqrt(rowsum(relu(H)))
    }
}

// ---------------- launch orchestration -------------------------------------
extern "C" void kernel_launch(void* const* d_in, const int* in_sizes, int n_in,
                              void* d_out, int out_size) {
    const float* x  = (const float*)d_in[0];
    const void*  ei = d_in[1];                 // int32 or int64 — detected on device
    const float* ew = (const float*)d_in[2];
    const float* Wx = (const float*)d_in[3];
    // d_in[4] = W_h : provably unused (H==0 => cheb(H,*) == bias)
    const float* bx = (const float*)d_in[5];
    const float* bh = (const float*)d_in[6];
    const float* Wl = (const float*)d_in[7];
    const float* bl = (const float*)d_in[8];
    float* out = (float*)d_out;
    (void)in_sizes; (void)n_in; (void)out_size;

    void *pXh, *pY1, *pY2, *pY3, *pdeg, *pcnt, *pany;
    cudaGetSymbolAddress(&pXh, g_xh);
    cudaGetSymbolAddress(&pY1, g_Y1);
    cudaGetSymbolAddress(&pY2, g_Y2);
    cudaGetSymbolAddress(&pY3, g_Y3);
    cudaGetSymbolAddress(&pdeg, g_deg);
    cudaGetSymbolAddress(&pcnt, g_cnt);
    cudaGetSymbolAddress(&pany, g_any);

    cudaFuncSetAttribute(k_gemm_mma, cudaFuncAttributeMaxDynamicSharedMemorySize, SM_DYN);

    // ---- prep: xcast(+detect) -> setflag -> pack -> deg -> scan -> scatter
    cudaMemsetAsync(pdeg, 0, (size_t)NN * sizeof(float));
    cudaMemsetAsync(pcnt, 0, (size_t)NN * sizeof(int));
    cudaMemsetAsync(pany, 0, sizeof(int));
    k_xcast  <<<(NN * FI / 4) / 256, 256>>>((const float4*)x, (const int*)ei);
    k_setflag<<<1, 1>>>();
    k_pack   <<<256, 256>>>(Wx, bx, bh);
    k_deg    <<<(NE / 2) / 256, 256>>>(ei, (const float2*)ew);
    k_scan   <<<1, 1024>>>();
    k_scatter<<<NE / 256, 256>>>(ei, ew);   // dinv fused (rsqrt inline)

    // ---- power basis: Y1 = L x ; Y2 = L Y1 ; Y3 = L Y2   (fp16 storage)
    k_spmm<<<NN / 8, 256>>>((const uint2*)pXh, (uint2*)pY1);
    k_spmm<<<NN / 8, 256>>>((const uint2*)pY1, (uint2*)pY2);
    k_spmm<<<NN / 8, 256>>>((const uint2*)pY2, (uint2*)pY3);

    // ---- fused mma.sync GEMM + GRU + head
    k_gemm_mma<<<NN / 128, 256, SM_DYN>>>(Wl, bl, out);
}

// round 13
// speedup vs baseline: 1.0668x; 1.0144x over previous
#include <cuda_runtime.h>
#include <cuda_fp16.h>
#include <cstdint>

#define NN 131072
#define NE 4194304
#define FI 64

// ---------------- scratch (device globals: no allocation allowed) ----------
__device__ float  g_deg [NN];        // raw weighted degree (by src)
__device__ int    g_cnt [NN];        // in-degree histogram (by dst)
__device__ int    g_off [NN + 1];    // CSR row offsets (by dst)
__device__ int    g_rank[NE];        // per-edge rank within its dst row
__device__ int2   g_edge[NE];        // CSR record: {src, weight-bits}
__device__ __half g_xh[NN * FI];     // x cast to fp16
__device__ __half g_Y1[NN * FI];     // Y1 = L x
__device__ __half g_Y2[NN * FI];     // Y2 = L Y1
__device__ __half g_Y3[NN * FI];     // Y3 = L Y2
// B operand [chunk kb][n 0..255][k 0..63] fp16, SW128-pre-swizzled (32KB/chunk)
__device__ __half g_B[4 * 256 * 64];
__device__ float  g_bias[256];       // b_x[g]+b_h[g] for gate0|gate2
__device__ int    g_any;             // detector: any odd word nonzero?
__device__ int    g_is64;            // 1 if edge_index is int64

// ---------------- edge-index access (dtype-robust, trap-proof) -------------
__device__ __forceinline__ int eidx(const void* ei, unsigned i) {
    int v;
    if (g_is64) v = (int)((const long long*)ei)[i];
    else        v = ((const int*)ei)[i];
    return v & (NN - 1);             // NN = 2^17: no-op for valid ids, trap-proof
}

// ---------------- helpers ----------------------------------------------------
__device__ __forceinline__ uint32_t smem_u32(const void* p) {
    uint32_t a;
    asm("{ .reg .u64 t; cvta.to.shared.u64 t, %1; cvt.u32.u64 %0, t; }"
        : "=r"(a) : "l"(p));
    return a;
}
#define SWZ128(o) ((o) ^ (((o) >> 3) & 0x70))

__device__ __forceinline__ void ldsm4(uint32_t& r0, uint32_t& r1, uint32_t& r2,
                                      uint32_t& r3, uint32_t addr) {
    asm volatile("ldmatrix.sync.aligned.m8n8.x4.shared.b16 {%0,%1,%2,%3}, [%4];"
                 : "=r"(r0), "=r"(r1), "=r"(r2), "=r"(r3) : "r"(addr));
}
__device__ __forceinline__ void mma16816(float* c, const uint32_t* a,
                                         uint32_t b0, uint32_t b1) {
    asm volatile("mma.sync.aligned.m16n8k16.row.col.f32.f16.f16.f32 "
                 "{%0,%1,%2,%3}, {%4,%5,%6,%7}, {%8,%9}, {%0,%1,%2,%3};"
                 : "+f"(c[0]), "+f"(c[1]), "+f"(c[2]), "+f"(c[3])
                 : "r"(a[0]), "r"(a[1]), "r"(a[2]), "r"(a[3]), "r"(b0), "r"(b1));
}
__device__ __forceinline__ void cpa16(uint32_t dst, const void* src) {
    asm volatile("cp.async.cg.shared.global [%0], [%1], 16;"
                 :: "r"(dst), "l"(src));
}
__device__ __forceinline__ float tanh_hw(float x) {
    float y;
    asm("tanh.approx.f32 %0, %1;" : "=f"(y) : "f"(x));
    return y;
}
// H = (1 - sigmoid(u)) * tanh(v), relu'd.
// 1 - sigmoid(u) = 0.5 - 0.5*tanh(u/2)  ->  2 HW tanh + 2 FMA (was ~8 MUFU)
__device__ __forceinline__ float gru_h(float u, float v) {
    float z1 = fmaf(-0.5f, tanh_hw(0.5f * u), 0.5f);
    return fmaxf(z1 * tanh_hw(v), 0.f);
}
__device__ __forceinline__ void acc_edge(float4& acc, int2 e,
                                         const uint2* __restrict__ vin, int lh) {
    uint2 u = vin[(long)e.x * 16 + lh];
    float w = __int_as_float(e.y);
    float2 f0 = __half22float2(*reinterpret_cast<__half2*>(&u.x));
    float2 f1 = __half22float2(*reinterpret_cast<__half2*>(&u.y));
    acc.x = fmaf(w, f0.x, acc.x); acc.y = fmaf(w, f0.y, acc.y);
    acc.z = fmaf(w, f1.x, acc.z); acc.w = fmaf(w, f1.y, acc.w);
}

// ---------------- prep kernels ---------------------------------------------
// x -> fp16 cast; blocks 0..15 additionally sample odd 32-bit words of the
// first 2*NE words of edge_index (all-zero <=> int64 layout)
__global__ void k_xcast(const float4* __restrict__ x, const int* __restrict__ w) {
    int i = blockIdx.x * 256 + threadIdx.x;      // NN*FI/4 threads
    float4 v = x[i];
    __half2 a = __floats2half2_rn(v.x, v.y);
    __half2 b = __floats2half2_rn(v.z, v.w);
    uint2 o;
    o.x = *reinterpret_cast<uint32_t*>(&a);
    o.y = *reinterpret_cast<uint32_t*>(&b);
    *reinterpret_cast<uint2*>(g_xh + (size_t)i * 4) = o;

    if (blockIdx.x < 16) {                       // fused dtype detector
        int t = blockIdx.x * 256 + threadIdx.x;  // 4096 samples
        int stride = (2 * (NE / 4096));
        int vv = w[(unsigned)(t * stride + 1)];
        if (__syncthreads_or(vv != 0) && threadIdx.x == 0) atomicOr(&g_any, 1);
    }
}

// weighted degree (by src) + in-degree histogram (by dst); histogram atomic's
// return value IS the CSR rank. 2 edges per thread, vectorized loads.
__global__ void k_deg(const void* __restrict__ ei, const float2* __restrict__ ew2) {
    unsigned t = blockIdx.x * 256 + threadIdx.x;     // NE/2 threads
    unsigned e = t * 2;
    int s0, s1, d0, d1;
    if (g_is64) {
        const longlong2* p = (const longlong2*)ei;
        longlong2 sv = p[t];
        longlong2 dv = p[(NE / 2) + t];
        s0 = (int)sv.x & (NN - 1); s1 = (int)sv.y & (NN - 1);
        d0 = (int)dv.x & (NN - 1); d1 = (int)dv.y & (NN - 1);
    } else {
        const int2* p = (const int2*)ei;
        int2 sv = p[t];
        int2 dv = p[(NE / 2) + t];
        s0 = sv.x & (NN - 1); s1 = sv.y & (NN - 1);
        d0 = dv.x & (NN - 1); d1 = dv.y & (NN - 1);
    }
    float2 w = ew2[t];
    atomicAdd(&g_deg[s0], w.x);
    atomicAdd(&g_deg[s1], w.y);
    g_rank[e]     = atomicAdd(&g_cnt[d0], 1);
    g_rank[e + 1] = atomicAdd(&g_cnt[d1], 1);
}

// single-block exclusive scan of g_cnt -> g_off  (1024 threads, distributed)
__global__ void k_scan() {
    __shared__ int wsum[32];
    __shared__ int carry_s;
    const int tid  = threadIdx.x;
    const int lane = tid & 31;
    const int w    = tid >> 5;
    int carry = 0;
    for (int base = 0; base < NN; base += 1024) {
        int v = g_cnt[base + tid];
        int x = v;
#pragma unroll
        for (int d = 1; d < 32; d <<= 1) {
            int y = __shfl_up_sync(0xffffffffu, x, d);
            if (lane >= d) x += y;
        }
        if (lane == 31) wsum[w] = x;
        __syncthreads();
        if (w == 0) {
            int s = wsum[lane];
#pragma unroll
            for (int d = 1; d < 32; d <<= 1) {
                int y = __shfl_up_sync(0xffffffffu, s, d);
                if (lane >= d) s += y;
            }
            wsum[lane] = s;
        }
        __syncthreads();
        int incl = x + (w > 0 ? wsum[w - 1] : 0) + carry;
        g_off[base + tid] = incl - v;
        if (tid == 1023) carry_s = incl;
        __syncthreads();
        carry = carry_s;
        __syncthreads();
    }
    if (tid == 0) g_off[NN] = carry;
}

// scatter edges into packed CSR records — NO atomics (rank precomputed);
// dinv fused: rsqrt applied to raw degrees inline (MUFU hidden under memory)
__global__ void k_scatter(const void* __restrict__ ei, const float* __restrict__ ew) {
    unsigned e = blockIdx.x * 256 + threadIdx.x;
    if (e >= NE) return;
    int s = eidx(ei, e);
    int d = eidx(ei, NE + e);
    float ds = g_deg[s], dd = g_deg[d];
    float is = (ds > 0.f) ? rsqrtf(ds) : 0.f;
    float id = (dd > 0.f) ? rsqrtf(dd) : 0.f;
    float w = -is * ew[e] * id;
    unsigned pos = (unsigned)(g_off[d] + g_rank[e]) & (NE - 1);  // trap-proof
    g_edge[pos] = make_int2(s, __float_as_int(w));
}

// Pack B: reparametrized Chebyshev weights (Y_k = L^k x basis), transposed
// [n][k], fp16, SW128-pre-swizzled.  Thread 0 also latches the dtype flag
// (runs after k_xcast's detector on-stream).
//   B0 = W0 - W2 ; B1 = W1 - 3*W3 ; B2 = 2*W2 ; B3 = 4*W3
__global__ void k_pack(const float* __restrict__ Wx, const float* __restrict__ bx,
                       const float* __restrict__ bh) {
    int i = blockIdx.x * 256 + threadIdx.x;   // 65536 total
    if (i == 0) g_is64 = (g_any == 0);        // fused setflag
    int kb = i >> 14, n = (i >> 6) & 255, kk = i & 63;
    int g  = (n < 128) ? 0 : 2;
    int jj = n & 127;
    const size_t base = (size_t)g * 4 * 64 * 128 + (size_t)kk * 128 + jj;
    const size_t kstep = (size_t)64 * 128;
    float w;
    if      (kb == 0) w = Wx[base]             - Wx[base + 2 * kstep];
    else if (kb == 1) w = Wx[base + kstep]     - 3.f * Wx[base + 3 * kstep];
    else if (kb == 2) w = 2.f * Wx[base + 2 * kstep];
    else              w = 4.f * Wx[base + 3 * kstep];
    uint32_t off = SWZ128((uint32_t)(n * 128 + kk * 2));   // byte off in 32KB tile
    g_B[(uint32_t)kb * 16384 + (off >> 1)] = __float2half(w);
    if (kb == 0 && kk == 0) g_bias[n] = bx[g * 128 + jj] + bh[g * 128 + jj];
}

// ---------------- SpMM gather (fp16 rows): out[d] = sum_e w_e * vin[src_e] --
// One warp per dst node; 2 half-warps × unroll-4 = 8 edges in flight per warp.
__global__ void __launch_bounds__(256)
k_spmm(const uint2* __restrict__ vin, uint2* __restrict__ vout) {
    const int node = blockIdx.x * 8 + (threadIdx.x >> 5);
    const int lane = threadIdx.x & 31;
    const int lh   = lane & 15;
    const int half = lane >> 4;
    const int beg = g_off[node];
    const int end = g_off[node + 1];

    float4 acc = make_float4(0.f, 0.f, 0.f, 0.f);
    int i = beg + half;
    for (; i + 6 < end; i += 8) {        // 4 edges per half-warp in flight
        int2 e0 = g_edge[i];
        int2 e1 = g_edge[i + 2];
        int2 e2 = g_edge[i + 4];
        int2 e3 = g_edge[i + 6];
        acc_edge(acc, e0, vin, lh);
        acc_edge(acc, e1, vin, lh);
        acc_edge(acc, e2, vin, lh);
        acc_edge(acc, e3, vin, lh);
    }
    for (; i < end; i += 2) {
        int2 e0 = g_edge[i];
        acc_edge(acc, e0, vin, lh);
    }
    acc.x += __shfl_xor_sync(0xffffffffu, acc.x, 16);
    acc.y += __shfl_xor_sync(0xffffffffu, acc.y, 16);
    acc.z += __shfl_xor_sync(0xffffffffu, acc.z, 16);
    acc.w += __shfl_xor_sync(0xffffffffu, acc.w, 16);

    if (half == 0) {
        __half2 h01 = __floats2half2_rn(acc.x, acc.y);
        __half2 h23 = __floats2half2_rn(acc.z, acc.w);
        uint2 o;
        o.x = *reinterpret_cast<uint32_t*>(&h01);
        o.y = *reinterpret_cast<uint32_t*>(&h23);
        vout[(long)node * 16 + lh] = o;
    }
}

// ---------------- mma.sync GEMM [128 rows/CTA, N=256, K=256] + GRU epilogue -
// A fp16, B fp16; fp32 accum. cp.async double-buffered (round-8 proven config).
// SMEM (dynamic): [0..1024) row-reduce; A ping-pong @1024 (2x16KB);
//                 B ping-pong @33792 (2x32KB). Total 99328 B.
#define SM_A0  1024
#define SM_B0  33792
#define SM_DYN 99328

__global__ void __launch_bounds__(256, 1)
k_gemm_mma(const float* __restrict__ Wlin, const float* __restrict__ blin,
           float* __restrict__ outbuf) {
    extern __shared__ char smem[];
    float* smf = (float*)smem;               // [0..128) rs, [128..256) dt
    const uint32_t sb  = smem_u32(smem);
    const int tid  = threadIdx.x;
    const int wid  = tid >> 5;
    const int lane = tid & 31;
    const int wm   = wid & 3;                // m quarter: rows wm*32..+31
    const int wn   = wid >> 2;               // n half pattern
    const long rowBase = (long)blockIdx.x * 128;

    if (tid < 128) { smf[tid] = 0.f; smf[128 + tid] = 0.f; }

    const __half* bases[4] = { g_xh + rowBase * FI, g_Y1 + rowBase * FI,
                               g_Y2 + rowBase * FI, g_Y3 + rowBase * FI };

    // async stage of chunk c into buffer b (A swizzled on the fly, B pre-swizzled)
    auto stage = [&](int c, int b) {
        const uint4* Asrc = (const uint4*)bases[c];
        uint32_t abase = sb + SM_A0 + (uint32_t)b * 16384;
#pragma unroll
        for (int it = 0; it < 4; it++) {
            int idx = tid + it * 256;           // 1024 uint4
            int r  = idx >> 3;
            int c8 = idx & 7;
            cpa16(abase + (uint32_t)(r * 128 + ((c8 ^ (r & 7)) << 4)), Asrc + idx);
        }
        const uint4* Bsrc = (const uint4*)(g_B + (size_t)c * 16384);
        uint32_t bbase = sb + SM_B0 + (uint32_t)b * 32768;
#pragma unroll
        for (int it = 0; it < 8; it++) {
            int idx = tid + it * 256;           // 2048 uint4
            cpa16(bbase + (uint32_t)idx * 16, Bsrc + idx);
        }
        asm volatile("cp.async.commit_group;");
    };

    float acc[2][16][4];
#pragma unroll
    for (int mt = 0; mt < 2; mt++)
#pragma unroll
        for (int t = 0; t < 16; t++)
#pragma unroll
            for (int q = 0; q < 4; q++) acc[mt][t][q] = 0.f;

    stage(0, 0);

#pragma unroll 1
    for (int c = 0; c < 4; c++) {
        const int cur = c & 1;
        if (c < 3) {
            stage(c + 1, cur ^ 1);
            asm volatile("cp.async.wait_group 1;");
        } else {
            asm volatile("cp.async.wait_group 0;");
        }
        __syncthreads();

        const uint32_t Aoff = SM_A0 + (uint32_t)cur * 16384;
        const uint32_t Boff = SM_B0 + (uint32_t)cur * 32768;
#pragma unroll
        for (int ks = 0; ks < 4; ks++) {
            uint32_t a[2][4];
#pragma unroll
            for (int mt = 0; mt < 2; mt++) {
                int r = wm * 32 + mt * 16 + (lane & 15);
                int g = 2 * ks + (lane >> 4);
                uint32_t ad = sb + Aoff + (uint32_t)(r * 128 + ((g ^ (r & 7)) << 4));
                ldsm4(a[mt][0], a[mt][1], a[mt][2], a[mt][3], ad);
            }
#pragma unroll
            for (int p = 0; p < 8; p++) {
                int tix = (p < 4) ? (2 * p) : (8 + 2 * (p - 4));
                int ntb = wn * 8 + ((p < 4) ? (2 * p) : (16 + 2 * (p - 4)));
                int n = ntb * 8 + (lane & 7) + ((lane >> 4) << 3);
                int g = 2 * ks + ((lane >> 3) & 1);
                uint32_t bd = sb + Boff + (uint32_t)(n * 128 + ((g ^ (n & 7)) << 4));
                uint32_t b0, b1, b2, b3;
                ldsm4(b0, b1, b2, b3, bd);
                mma16816(acc[0][tix],     a[0], b0, b1);
                mma16816(acc[1][tix],     a[1], b0, b1);
                mma16816(acc[0][tix + 1], a[0], b2, b3);
                mma16816(acc[1][tix + 1], a[1], b2, b3);
            }
        }
        __syncthreads();
    }

    // ---- GRU epilogue on register accumulators (HW tanh) -------------------
    const float bl = __ldg(blin);
#pragma unroll
    for (int mt = 0; mt < 2; mt++) {
        float rs0 = 0.f, dt0 = 0.f, rs1 = 0.f, dt1 = 0.f;
#pragma unroll
        for (int i = 0; i < 8; i++) {
            int j0 = wn * 64 + i * 8 + 2 * (lane & 3);
            float bu0 = __ldg(g_bias + j0),       bu1 = __ldg(g_bias + j0 + 1);
            float bv0 = __ldg(g_bias + j0 + 128), bv1 = __ldg(g_bias + j0 + 129);
            float w0  = __ldg(Wlin + j0),         w1  = __ldg(Wlin + j0 + 1);
            float h00 = gru_h(acc[mt][i][0] + bu0, acc[mt][8 + i][0] + bv0);
            float h01 = gru_h(acc[mt][i][1] + bu1, acc[mt][8 + i][1] + bv1);
            float h10 = gru_h(acc[mt][i][2] + bu0, acc[mt][8 + i][2] + bv0);
            float h11 = gru_h(acc[mt][i][3] + bu1, acc[mt][8 + i][3] + bv1);
            rs0 += h00 + h01; dt0 = fmaf(h00, w0, fmaf(h01, w1, dt0));
            rs1 += h10 + h11; dt1 = fmaf(h10, w0, fmaf(h11, w1, dt1));
        }
#pragma unroll
        for (int s = 1; s < 4; s <<= 1) {
            rs0 += __shfl_xor_sync(0xffffffffu, rs0, s);
            dt0 += __shfl_xor_sync(0xffffffffu, dt0, s);
            rs1 += __shfl_xor_sync(0xffffffffu, rs1, s);
            dt1 += __shfl_xor_sync(0xffffffffu, dt1, s);
        }
        if ((lane & 3) == 0) {
            int r = wm * 32 + mt * 16 + (lane >> 2);
            atomicAdd(&smf[r],           rs0);
            atomicAdd(&smf[128 + r],     dt0);
            atomicAdd(&smf[r + 8],       rs1);
            atomicAdd(&smf[128 + r + 8], dt1);
        }
    }
    __syncthreads();
    if (tid < 128) {
        long grow = rowBase + tid;
        outbuf[grow]      = smf[128 + tid] + bl;   // out = h @ W_lin + b_lin
        outbuf[NN + grow] = sqrtf(smf[tid]);       // logits = sqrt(rowsum(relu(H)))
    }
}

// ---------------- launch orchestration -------------------------------------
extern "C" void kernel_launch(void* const* d_in, const int* in_sizes, int n_in,
                              void* d_out, int out_size) {
    const float* x  = (const float*)d_in[0];
    const void*  ei = d_in[1];                 // int32 or int64 — detected on device
    const float* ew = (const float*)d_in[2];
    const float* Wx = (const float*)d_in[3];
    // d_in[4] = W_h : provably unused (H==0 => cheb(H,*) == bias)
    const float* bx = (const float*)d_in[5];
    const float* bh = (const float*)d_in[6];
    const float* Wl = (const float*)d_in[7];
    const float* bl = (const float*)d_in[8];
    float* out = (float*)d_out;
    (void)in_sizes; (void)n_in; (void)out_size;

    void *pXh, *pY1, *pY2, *pY3, *pdeg, *pcnt, *pany;
    cudaGetSymbolAddress(&pXh, g_xh);
    cudaGetSymbolAddress(&pY1, g_Y1);
    cudaGetSymbolAddress(&pY2, g_Y2);
    cudaGetSymbolAddress(&pY3, g_Y3);
    cudaGetSymbolAddress(&pdeg, g_deg);
    cudaGetSymbolAddress(&pcnt, g_cnt);
    cudaGetSymbolAddress(&pany, g_any);

    cudaFuncSetAttribute(k_gemm_mma, cudaFuncAttributeMaxDynamicSharedMemorySize, SM_DYN);

    // ---- prep: xcast(+detect) -> pack(+setflag) -> deg -> scan -> scatter
    cudaMemsetAsync(pdeg, 0, (size_t)NN * sizeof(float));
    cudaMemsetAsync(pcnt, 0, (size_t)NN * sizeof(int));
    cudaMemsetAsync(pany, 0, sizeof(int));
    k_xcast  <<<(NN * FI / 4) / 256, 256>>>((const float4*)x, (const int*)ei);
    k_pack   <<<256, 256>>>(Wx, bx, bh);   // also latches g_is64
    k_deg    <<<(NE / 2) / 256, 256>>>(ei, (const float2*)ew);
    k_scan   <<<1, 1024>>>();
    k_scatter<<<NE / 256, 256>>>(ei, ew);  // dinv fused (rsqrt inline)

    // ---- power basis: Y1 = L x ; Y2 = L Y1 ; Y3 = L Y2   (fp16 storage)
    k_spmm<<<NN / 8, 256>>>((const uint2*)pXh, (uint2*)pY1);
    k_spmm<<<NN / 8, 256>>>((const uint2*)pY1, (uint2*)pY2);
    k_spmm<<<NN / 8, 256>>>((const uint2*)pY2, (uint2*)pY3);

    // ---- fused mma.sync GEMM + GRU + head
    k_gemm_mma<<<NN / 128, 256, SM_DYN>>>(Wl, bl, out);
}

// round 14
// speedup vs baseline: 1.2764x; 1.1965x over previous
#include <cuda_runtime.h>
#include <cuda_fp16.h>
#include <cstdint>

#define NN 131072
#define NE 4194304
#define FI 64

// ---------------- scratch (device globals: no allocation allowed) ----------
__device__ float  g_deg [NN];        // raw weighted degree (by src)
__device__ int    g_cnt [NN];        // in-degree histogram (by dst)
__device__ int    g_off [NN + 1];    // CSR row offsets (by dst)
__device__ int    g_bsum[128];       // per-scan-block totals -> exclusive offsets
__device__ int    g_rank[NE];        // per-edge rank within its dst row
__device__ int2   g_edge[NE];        // CSR record: {src, weight-bits}
__device__ __half g_xh[NN * FI];     // x cast to fp16
__device__ __half g_Y1[NN * FI];     // Y1 = L x
__device__ __half g_Y2[NN * FI];     // Y2 = L Y1
__device__ __half g_Y3[NN * FI];     // Y3 = L Y2
// B operand [chunk kb][n 0..255][k 0..63] fp16, SW128-pre-swizzled (32KB/chunk)
__device__ __half g_B[4 * 256 * 64];
__device__ float  g_bias[256];       // b_x[g]+b_h[g] for gate0|gate2
__device__ int    g_any;             // detector: any odd word nonzero?
__device__ int    g_is64;            // 1 if edge_index is int64

// ---------------- edge-index access (dtype-robust, trap-proof) -------------
__device__ __forceinline__ int eidx(const void* ei, unsigned i) {
    int v;
    if (g_is64) v = (int)((const long long*)ei)[i];
    else        v = ((const int*)ei)[i];
    return v & (NN - 1);             // NN = 2^17: no-op for valid ids, trap-proof
}

// ---------------- helpers ----------------------------------------------------
__device__ __forceinline__ uint32_t smem_u32(const void* p) {
    uint32_t a;
    asm("{ .reg .u64 t; cvta.to.shared.u64 t, %1; cvt.u32.u64 %0, t; }"
        : "=r"(a) : "l"(p));
    return a;
}
#define SWZ128(o) ((o) ^ (((o) >> 3) & 0x70))

__device__ __forceinline__ void ldsm4(uint32_t& r0, uint32_t& r1, uint32_t& r2,
                                      uint32_t& r3, uint32_t addr) {
    asm volatile("ldmatrix.sync.aligned.m8n8.x4.shared.b16 {%0,%1,%2,%3}, [%4];"
                 : "=r"(r0), "=r"(r1), "=r"(r2), "=r"(r3) : "r"(addr));
}
__device__ __forceinline__ void mma16816(float* c, const uint32_t* a,
                                         uint32_t b0, uint32_t b1) {
    asm volatile("mma.sync.aligned.m16n8k16.row.col.f32.f16.f16.f32 "
                 "{%0,%1,%2,%3}, {%4,%5,%6,%7}, {%8,%9}, {%0,%1,%2,%3};"
                 : "+f"(c[0]), "+f"(c[1]), "+f"(c[2]), "+f"(c[3])
                 : "r"(a[0]), "r"(a[1]), "r"(a[2]), "r"(a[3]), "r"(b0), "r"(b1));
}
__device__ __forceinline__ void cpa16(uint32_t dst, const void* src) {
    asm volatile("cp.async.cg.shared.global [%0], [%1], 16;"
                 :: "r"(dst), "l"(src));
}
__device__ __forceinline__ float tanh_hw(float x) {
    float y;
    asm("tanh.approx.f32 %0, %1;" : "=f"(y) : "f"(x));
    return y;
}
// H = (1 - sigmoid(u)) * tanh(v), relu'd.
// 1 - sigmoid(u) = 0.5 - 0.5*tanh(u/2)  ->  2 HW tanh + 2 FMA
__device__ __forceinline__ float gru_h(float u, float v) {
    float z1 = fmaf(-0.5f, tanh_hw(0.5f * u), 0.5f);
    return fmaxf(z1 * tanh_hw(v), 0.f);
}
__device__ __forceinline__ void acc_edge(float4& acc, int2 e,
                                         const uint2* __restrict__ vin, int lh) {
    uint2 u = vin[(long)e.x * 16 + lh];
    float w = __int_as_float(e.y);
    float2 f0 = __half22float2(*reinterpret_cast<__half2*>(&u.x));
    float2 f1 = __half22float2(*reinterpret_cast<__half2*>(&u.y));
    acc.x = fmaf(w, f0.x, acc.x); acc.y = fmaf(w, f0.y, acc.y);
    acc.z = fmaf(w, f1.x, acc.z); acc.w = fmaf(w, f1.y, acc.w);
}

// ---------------- prep kernels ---------------------------------------------
// x -> fp16 cast; blocks 0..15 additionally sample odd 32-bit words of the
// first 2*NE words of edge_index (all-zero <=> int64 layout)
__global__ void k_xcast(const float4* __restrict__ x, const int* __restrict__ w) {
    int i = blockIdx.x * 256 + threadIdx.x;      // NN*FI/4 threads
    float4 v = x[i];
    __half2 a = __floats2half2_rn(v.x, v.y);
    __half2 b = __floats2half2_rn(v.z, v.w);
    uint2 o;
    o.x = *reinterpret_cast<uint32_t*>(&a);
    o.y = *reinterpret_cast<uint32_t*>(&b);
    *reinterpret_cast<uint2*>(g_xh + (size_t)i * 4) = o;

    if (blockIdx.x < 16) {                       // fused dtype detector
        int t = blockIdx.x * 256 + threadIdx.x;  // 4096 samples
        int stride = (2 * (NE / 4096));
        int vv = w[(unsigned)(t * stride + 1)];
        if (__syncthreads_or(vv != 0) && threadIdx.x == 0) atomicOr(&g_any, 1);
    }
}

// weighted degree (by src) + in-degree histogram (by dst); histogram atomic's
// return value IS the CSR rank. 2 edges per thread, vectorized loads.
__global__ void k_deg(const void* __restrict__ ei, const float2* __restrict__ ew2) {
    unsigned t = blockIdx.x * 256 + threadIdx.x;     // NE/2 threads
    unsigned e = t * 2;
    int s0, s1, d0, d1;
    if (g_is64) {
        const longlong2* p = (const longlong2*)ei;
        longlong2 sv = p[t];
        longlong2 dv = p[(NE / 2) + t];
        s0 = (int)sv.x & (NN - 1); s1 = (int)sv.y & (NN - 1);
        d0 = (int)dv.x & (NN - 1); d1 = (int)dv.y & (NN - 1);
    } else {
        const int2* p = (const int2*)ei;
        int2 sv = p[t];
        int2 dv = p[(NE / 2) + t];
        s0 = sv.x & (NN - 1); s1 = sv.y & (NN - 1);
        d0 = dv.x & (NN - 1); d1 = dv.y & (NN - 1);
    }
    float2 w = ew2[t];
    atomicAdd(&g_deg[s0], w.x);
    atomicAdd(&g_deg[s1], w.y);
    g_rank[e]     = atomicAdd(&g_cnt[d0], 1);
    g_rank[e + 1] = atomicAdd(&g_cnt[d1], 1);
}

// ---- parallel 3-phase exclusive scan of g_cnt -> g_off ---------------------
// Phase A: 128 blocks x 1024 threads: block-local exclusive scan + block total
__global__ void __launch_bounds__(1024) k_scanA() {
    __shared__ int wsum[32];
    const int tid  = threadIdx.x;
    const int lane = tid & 31;
    const int w    = tid >> 5;
    const int gid  = blockIdx.x * 1024 + tid;
    int v = g_cnt[gid];
    int x = v;
#pragma unroll
    for (int d = 1; d < 32; d <<= 1) {
        int y = __shfl_up_sync(0xffffffffu, x, d);
        if (lane >= d) x += y;
    }
    if (lane == 31) wsum[w] = x;
    __syncthreads();
    if (w == 0) {
        int s = wsum[lane];
#pragma unroll
        for (int d = 1; d < 32; d <<= 1) {
            int y = __shfl_up_sync(0xffffffffu, s, d);
            if (lane >= d) s += y;
        }
        wsum[lane] = s;
    }
    __syncthreads();
    int incl = x + (w > 0 ? wsum[w - 1] : 0);
    g_off[gid] = incl - v;                     // block-local exclusive
    if (tid == 1023) g_bsum[blockIdx.x] = incl;
}

// Phase B: 1 block x 128 threads: exclusive scan of the 128 block totals
__global__ void k_scanB() {
    __shared__ int ws[4];
    const int tid  = threadIdx.x;
    const int lane = tid & 31;
    const int w    = tid >> 5;
    int v = g_bsum[tid];
    int x = v;
#pragma unroll
    for (int d = 1; d < 32; d <<= 1) {
        int y = __shfl_up_sync(0xffffffffu, x, d);
        if (lane >= d) x += y;
    }
    if (lane == 31) ws[w] = x;
    __syncthreads();
    int add = 0;
#pragma unroll
    for (int i = 0; i < 4; i++)
        if (i < w) add += ws[i];
    g_bsum[tid] = x - v + add;                 // exclusive block offset
    if (tid == 127) g_off[NN] = x + add;       // grand total
}

// Phase C: add block offsets into g_off (final CSR offsets)
__global__ void k_scanC() {
    int gid = blockIdx.x * 256 + threadIdx.x;  // NN threads
    g_off[gid] += g_bsum[gid >> 10];
}

// scatter edges into packed CSR records — NO atomics (rank precomputed);
// dinv fused: rsqrt applied to raw degrees inline (MUFU hidden under memory)
__global__ void k_scatter(const void* __restrict__ ei, const float* __restrict__ ew) {
    unsigned e = blockIdx.x * 256 + threadIdx.x;
    if (e >= NE) return;
    int s = eidx(ei, e);
    int d = eidx(ei, NE + e);
    float ds = g_deg[s], dd = g_deg[d];
    float is = (ds > 0.f) ? rsqrtf(ds) : 0.f;
    float id = (dd > 0.f) ? rsqrtf(dd) : 0.f;
    float w = -is * ew[e] * id;
    unsigned pos = (unsigned)(g_off[d] + g_rank[e]) & (NE - 1);  // trap-proof
    g_edge[pos] = make_int2(s, __float_as_int(w));
}

// Pack B: reparametrized Chebyshev weights (Y_k = L^k x basis), transposed
// [n][k], fp16, SW128-pre-swizzled.  Thread 0 also latches the dtype flag.
//   B0 = W0 - W2 ; B1 = W1 - 3*W3 ; B2 = 2*W2 ; B3 = 4*W3
__global__ void k_pack(const float* __restrict__ Wx, const float* __restrict__ bx,
                       const float* __restrict__ bh) {
    int i = blockIdx.x * 256 + threadIdx.x;   // 65536 total
    if (i == 0) g_is64 = (g_any == 0);        // fused setflag
    int kb = i >> 14, n = (i >> 6) & 255, kk = i & 63;
    int g  = (n < 128) ? 0 : 2;
    int jj = n & 127;
    const size_t base = (size_t)g * 4 * 64 * 128 + (size_t)kk * 128 + jj;
    const size_t kstep = (size_t)64 * 128;
    float w;
    if      (kb == 0) w = Wx[base]             - Wx[base + 2 * kstep];
    else if (kb == 1) w = Wx[base + kstep]     - 3.f * Wx[base + 3 * kstep];
    else if (kb == 2) w = 2.f * Wx[base + 2 * kstep];
    else              w = 4.f * Wx[base + 3 * kstep];
    uint32_t off = SWZ128((uint32_t)(n * 128 + kk * 2));   // byte off in 32KB tile
    g_B[(uint32_t)kb * 16384 + (off >> 1)] = __float2half(w);
    if (kb == 0 && kk == 0) g_bias[n] = bx[g * 128 + jj] + bh[g * 128 + jj];
}

// ---------------- SpMM gather (fp16 rows): out[d] = sum_e w_e * vin[src_e] --
// One warp per dst node; 2 half-warps × unroll-4 = 8 edges in flight per warp.
__global__ void __launch_bounds__(256)
k_spmm(const uint2* __restrict__ vin, uint2* __restrict__ vout) {
    const int node = blockIdx.x * 8 + (threadIdx.x >> 5);
    const int lane = threadIdx.x & 31;
    const int lh   = lane & 15;
    const int half = lane >> 4;
    const int beg = g_off[node];
    const int end = g_off[node + 1];

    float4 acc = make_float4(0.f, 0.f, 0.f, 0.f);
    int i = beg + half;
    for (; i + 6 < end; i += 8) {        // 4 edges per half-warp in flight
        int2 e0 = g_edge[i];
        int2 e1 = g_edge[i + 2];
        int2 e2 = g_edge[i + 4];
        int2 e3 = g_edge[i + 6];
        acc_edge(acc, e0, vin, lh);
        acc_edge(acc, e1, vin, lh);
        acc_edge(acc, e2, vin, lh);
        acc_edge(acc, e3, vin, lh);
    }
    for (; i < end; i += 2) {
        int2 e0 = g_edge[i];
        acc_edge(acc, e0, vin, lh);
    }
    acc.x += __shfl_xor_sync(0xffffffffu, acc.x, 16);
    acc.y += __shfl_xor_sync(0xffffffffu, acc.y, 16);
    acc.z += __shfl_xor_sync(0xffffffffu, acc.z, 16);
    acc.w += __shfl_xor_sync(0xffffffffu, acc.w, 16);

    if (half == 0) {
        __half2 h01 = __floats2half2_rn(acc.x, acc.y);
        __half2 h23 = __floats2half2_rn(acc.z, acc.w);
        uint2 o;
        o.x = *reinterpret_cast<uint32_t*>(&h01);
        o.y = *reinterpret_cast<uint32_t*>(&h23);
        vout[(long)node * 16 + lh] = o;
    }
}

// ---------------- mma.sync GEMM [128 rows/CTA, N=256, K=256] + GRU epilogue -
// A fp16, B fp16; fp32 accum. cp.async double-buffered (round-8 proven config).
// SMEM (dynamic): [0..1024) row-reduce; A ping-pong @1024 (2x16KB);
//                 B ping-pong @33792 (2x32KB). Total 99328 B.
#define SM_A0  1024
#define SM_B0  33792
#define SM_DYN 99328

__global__ void __launch_bounds__(256, 1)
k_gemm_mma(const float* __restrict__ Wlin, const float* __restrict__ blin,
           float* __restrict__ outbuf) {
    extern __shared__ char smem[];
    float* smf = (float*)smem;               // [0..128) rs, [128..256) dt
    const uint32_t sb  = smem_u32(smem);
    const int tid  = threadIdx.x;
    const int wid  = tid >> 5;
    const int lane = tid & 31;
    const int wm   = wid & 3;                // m quarter: rows wm*32..+31
    const int wn   = wid >> 2;               // n half pattern
    const long rowBase = (long)blockIdx.x * 128;

    if (tid < 128) { smf[tid] = 0.f; smf[128 + tid] = 0.f; }

    const __half* bases[4] = { g_xh + rowBase * FI, g_Y1 + rowBase * FI,
                               g_Y2 + rowBase * FI, g_Y3 + rowBase * FI };

    // async stage of chunk c into buffer b (A swizzled on the fly, B pre-swizzled)
    auto stage = [&](int c, int b) {
        const uint4* Asrc = (const uint4*)bases[c];
        uint32_t abase = sb + SM_A0 + (uint32_t)b * 16384;
#pragma unroll
        for (int it = 0; it < 4; it++) {
            int idx = tid + it * 256;           // 1024 uint4
            int r  = idx >> 3;
            int c8 = idx & 7;
            cpa16(abase + (uint32_t)(r * 128 + ((c8 ^ (r & 7)) << 4)), Asrc + idx);
        }
        const uint4* Bsrc = (const uint4*)(g_B + (size_t)c * 16384);
        uint32_t bbase = sb + SM_B0 + (uint32_t)b * 32768;
#pragma unroll
        for (int it = 0; it < 8; it++) {
            int idx = tid + it * 256;           // 2048 uint4
            cpa16(bbase + (uint32_t)idx * 16, Bsrc + idx);
        }
        asm volatile("cp.async.commit_group;");
    };

    float acc[2][16][4];
#pragma unroll
    for (int mt = 0; mt < 2; mt++)
#pragma unroll
        for (int t = 0; t < 16; t++)
#pragma unroll
            for (int q = 0; q < 4; q++) acc[mt][t][q] = 0.f;

    stage(0, 0);

#pragma unroll 1
    for (int c = 0; c < 4; c++) {
        const int cur = c & 1;
        if (c < 3) {
            stage(c + 1, cur ^ 1);
            asm volatile("cp.async.wait_group 1;");
        } else {
            asm volatile("cp.async.wait_group 0;");
        }
        __syncthreads();

        const uint32_t Aoff = SM_A0 + (uint32_t)cur * 16384;
        const uint32_t Boff = SM_B0 + (uint32_t)cur * 32768;
#pragma unroll
        for (int ks = 0; ks < 4; ks++) {
            uint32_t a[2][4];
#pragma unroll
            for (int mt = 0; mt < 2; mt++) {
                int r = wm * 32 + mt * 16 + (lane & 15);
                int g = 2 * ks + (lane >> 4);
                uint32_t ad = sb + Aoff + (uint32_t)(r * 128 + ((g ^ (r & 7)) << 4));
                ldsm4(a[mt][0], a[mt][1], a[mt][2], a[mt][3], ad);
            }
#pragma unroll
            for (int p = 0; p < 8; p++) {
                int tix = (p < 4) ? (2 * p) : (8 + 2 * (p - 4));
                int ntb = wn * 8 + ((p < 4) ? (2 * p) : (16 + 2 * (p - 4)));
                int n = ntb * 8 + (lane & 7) + ((lane >> 4) << 3);
                int g = 2 * ks + ((lane >> 3) & 1);
                uint32_t bd = sb + Boff + (uint32_t)(n * 128 + ((g ^ (n & 7)) << 4));
                uint32_t b0, b1, b2, b3;
                ldsm4(b0, b1, b2, b3, bd);
                mma16816(acc[0][tix],     a[0], b0, b1);
                mma16816(acc[1][tix],     a[1], b0, b1);
                mma16816(acc[0][tix + 1], a[0], b2, b3);
                mma16816(acc[1][tix + 1], a[1], b2, b3);
            }
        }
        __syncthreads();
    }

    // ---- GRU epilogue on register accumulators (HW tanh) -------------------
    const float bl = __ldg(blin);
#pragma unroll
    for (int mt = 0; mt < 2; mt++) {
        float rs0 = 0.f, dt0 = 0.f, rs1 = 0.f, dt1 = 0.f;
#pragma unroll
        for (int i = 0; i < 8; i++) {
            int j0 = wn * 64 + i * 8 + 2 * (lane & 3);
            float bu0 = __ldg(g_bias + j0),       bu1 = __ldg(g_bias + j0 + 1);
            float bv0 = __ldg(g_bias + j0 + 128), bv1 = __ldg(g_bias + j0 + 129);
            float w0  = __ldg(Wlin + j0),         w1  = __ldg(Wlin + j0 + 1);
            float h00 = gru_h(acc[mt][i][0] + bu0, acc[mt][8 + i][0] + bv0);
            float h01 = gru_h(acc[mt][i][1] + bu1, acc[mt][8 + i][1] + bv1);
            float h10 = gru_h(acc[mt][i][2] + bu0, acc[mt][8 + i][2] + bv0);
            float h11 = gru_h(acc[mt][i][3] + bu1, acc[mt][8 + i][3] + bv1);
            rs0 += h00 + h01; dt0 = fmaf(h00, w0, fmaf(h01, w1, dt0));
            rs1 += h10 + h11; dt1 = fmaf(h10, w0, fmaf(h11, w1, dt1));
        }
#pragma unroll
        for (int s = 1; s < 4; s <<= 1) {
            rs0 += __shfl_xor_sync(0xffffffffu, rs0, s);
            dt0 += __shfl_xor_sync(0xffffffffu, dt0, s);
            rs1 += __shfl_xor_sync(0xffffffffu, rs1, s);
            dt1 += __shfl_xor_sync(0xffffffffu, dt1, s);
        }
        if ((lane & 3) == 0) {
            int r = wm * 32 + mt * 16 + (lane >> 2);
            atomicAdd(&smf[r],           rs0);
            atomicAdd(&smf[128 + r],     dt0);
            atomicAdd(&smf[r + 8],       rs1);
            atomicAdd(&smf[128 + r + 8], dt1);
        }
    }
    __syncthreads();
    if (tid < 128) {
        long grow = rowBase + tid;
        outbuf[grow]      = smf[128 + tid] + bl;   // out = h @ W_lin + b_lin
        outbuf[NN + grow] = sqrtf(smf[tid]);       // logits = sqrt(rowsum(relu(H)))
    }
}

// ---------------- launch orchestration -------------------------------------
extern "C" void kernel_launch(void* const* d_in, const int* in_sizes, int n_in,
                              void* d_out, int out_size) {
    const float* x  = (const float*)d_in[0];
    const void*  ei = d_in[1];                 // int32 or int64 — detected on device
    const float* ew = (const float*)d_in[2];
    const float* Wx = (const float*)d_in[3];
    // d_in[4] = W_h : provably unused (H==0 => cheb(H,*) == bias)
    const float* bx = (const float*)d_in[5];
    const float* bh = (const float*)d_in[6];
    const float* Wl = (const float*)d_in[7];
    const float* bl = (const float*)d_in[8];
    float* out = (float*)d_out;
    (void)in_sizes; (void)n_in; (void)out_size;

    void *pXh, *pY1, *pY2, *pY3, *pdeg, *pcnt, *pany;
    cudaGetSymbolAddress(&pXh, g_xh);
    cudaGetSymbolAddress(&pY1, g_Y1);
    cudaGetSymbolAddress(&pY2, g_Y2);
    cudaGetSymbolAddress(&pY3, g_Y3);
    cudaGetSymbolAddress(&pdeg, g_deg);
    cudaGetSymbolAddress(&pcnt, g_cnt);
    cudaGetSymbolAddress(&pany, g_any);

    cudaFuncSetAttribute(k_gemm_mma, cudaFuncAttributeMaxDynamicSharedMemorySize, SM_DYN);

    // ---- prep: xcast(+detect) -> pack(+setflag) -> deg -> scanA/B/C -> scatter
    cudaMemsetAsync(pdeg, 0, (size_t)NN * sizeof(float));
    cudaMemsetAsync(pcnt, 0, (size_t)NN * sizeof(int));
    cudaMemsetAsync(pany, 0, sizeof(int));
    k_xcast  <<<(NN * FI / 4) / 256, 256>>>((const float4*)x, (const int*)ei);
    k_pack   <<<256, 256>>>(Wx, bx, bh);   // also latches g_is64
    k_deg    <<<(NE / 2) / 256, 256>>>(ei, (const float2*)ew);
    k_scanA  <<<NN / 1024, 1024>>>();
    k_scanB  <<<1, 128>>>();
    k_scanC  <<<NN / 256, 256>>>();
    k_scatter<<<NE / 256, 256>>>(ei, ew);  // dinv fused (rsqrt inline)

    // ---- power basis: Y1 = L x ; Y2 = L Y1 ; Y3 = L Y2   (fp16 storage)
    k_spmm<<<NN / 8, 256>>>((const uint2*)pXh, (uint2*)pY1);
    k_spmm<<<NN / 8, 256>>>((const uint2*)pY1, (uint2*)pY2);
    k_spmm<<<NN / 8, 256>>>((const uint2*)pY2, (uint2*)pY3);

    // ---- fused mma.sync GEMM + GRU + head
    k_gemm_mma<<<NN / 128, 256, SM_DYN>>>(Wl, bl, out);
}

// round 15
// speedup vs baseline: 1.3073x; 1.0242x over previous
#include <cuda_runtime.h>
#include <cuda_fp16.h>
#include <cstdint>

#define NN 131072
#define NE 4194304
#define FI 64

// ---------------- scratch (device globals: no allocation allowed) ----------
__device__ float  g_deg [NN];        // raw weighted degree (by src)
__device__ int    g_cnt [NN];        // in-degree histogram (by dst)
__device__ int    g_off [NN + 1];    // CSR row offsets (by dst)
__device__ int    g_bsum[128];       // per-scan-block totals
__device__ int    g_rank[NE];        // per-edge rank within its dst row
__device__ int2   g_edge[NE];        // CSR record: {src, weight-bits}
__device__ __half g_xh[NN * FI];     // x cast to fp16
__device__ __half g_Y1[NN * FI];     // Y1 = L x
__device__ __half g_Y2[NN * FI];     // Y2 = L Y1
__device__ __half g_Y3[NN * FI];     // Y3 = L Y2
// B operand [chunk kb][n 0..255][k 0..63] fp16, SW128-pre-swizzled (32KB/chunk)
__device__ __half g_B[4 * 256 * 64];
__device__ float  g_bias[256];       // b_x[g]+b_h[g] for gate0|gate2
__device__ int    g_any;             // static-zero init; idempotent OR across runs
__device__ int    g_is64;            // 1 if edge_index is int64

// ---------------- edge-index access (dtype-robust, trap-proof) -------------
__device__ __forceinline__ int eidx(const void* ei, unsigned i) {
    int v;
    if (g_is64) v = (int)((const long long*)ei)[i];
    else        v = ((const int*)ei)[i];
    return v & (NN - 1);             // NN = 2^17: no-op for valid ids, trap-proof
}

// ---------------- helpers ----------------------------------------------------
__device__ __forceinline__ uint32_t smem_u32(const void* p) {
    uint32_t a;
    asm("{ .reg .u64 t; cvta.to.shared.u64 t, %1; cvt.u32.u64 %0, t; }"
        : "=r"(a) : "l"(p));
    return a;
}
#define SWZ128(o) ((o) ^ (((o) >> 3) & 0x70))

__device__ __forceinline__ void ldsm4(uint32_t& r0, uint32_t& r1, uint32_t& r2,
                                      uint32_t& r3, uint32_t addr) {
    asm volatile("ldmatrix.sync.aligned.m8n8.x4.shared.b16 {%0,%1,%2,%3}, [%4];"
                 : "=r"(r0), "=r"(r1), "=r"(r2), "=r"(r3) : "r"(addr));
}
__device__ __forceinline__ void mma16816(float* c, const uint32_t* a,
                                         uint32_t b0, uint32_t b1) {
    asm volatile("mma.sync.aligned.m16n8k16.row.col.f32.f16.f16.f32 "
                 "{%0,%1,%2,%3}, {%4,%5,%6,%7}, {%8,%9}, {%0,%1,%2,%3};"
                 : "+f"(c[0]), "+f"(c[1]), "+f"(c[2]), "+f"(c[3])
                 : "r"(a[0]), "r"(a[1]), "r"(a[2]), "r"(a[3]), "r"(b0), "r"(b1));
}
__device__ __forceinline__ void cpa16(uint32_t dst, const void* src) {
    asm volatile("cp.async.cg.shared.global [%0], [%1], 16;"
                 :: "r"(dst), "l"(src));
}
__device__ __forceinline__ float tanh_hw(float x) {
    float y;
    asm("tanh.approx.f32 %0, %1;" : "=f"(y) : "f"(x));
    return y;
}
// H = (1 - sigmoid(u)) * tanh(v), relu'd.
// 1 - sigmoid(u) = 0.5 - 0.5*tanh(u/2)  ->  2 HW tanh + 2 FMA
__device__ __forceinline__ float gru_h(float u, float v) {
    float z1 = fmaf(-0.5f, tanh_hw(0.5f * u), 0.5f);
    return fmaxf(z1 * tanh_hw(v), 0.f);
}
__device__ __forceinline__ void acc_edge(float4& acc, int2 e,
                                         const uint2* __restrict__ vin, int lh) {
    uint2 u = vin[(long)e.x * 16 + lh];
    float w = __int_as_float(e.y);
    float2 f0 = __half22float2(*reinterpret_cast<__half2*>(&u.x));
    float2 f1 = __half22float2(*reinterpret_cast<__half2*>(&u.y));
    acc.x = fmaf(w, f0.x, acc.x); acc.y = fmaf(w, f0.y, acc.y);
    acc.z = fmaf(w, f1.x, acc.z); acc.w = fmaf(w, f1.y, acc.w);
}

// ---------------- prep kernels ---------------------------------------------
// x -> fp16 cast; ALSO zeroes g_deg/g_cnt (first 32K threads) and runs the
// dtype detector (blocks 0..15). g_any is static-zero + idempotent OR.
__global__ void k_xcast(const float4* __restrict__ x, const int* __restrict__ w) {
    int i = blockIdx.x * 256 + threadIdx.x;      // NN*FI/4 = 2M threads
    float4 v = x[i];
    __half2 a = __floats2half2_rn(v.x, v.y);
    __half2 b = __floats2half2_rn(v.z, v.w);
    uint2 o;
    o.x = *reinterpret_cast<uint32_t*>(&a);
    o.y = *reinterpret_cast<uint32_t*>(&b);
    *reinterpret_cast<uint2*>(g_xh + (size_t)i * 4) = o;

    if (i < NN / 4) {                            // fused zeroing (NN/4 float4/int4)
        ((float4*)g_deg)[i] = make_float4(0.f, 0.f, 0.f, 0.f);
        ((int4*)g_cnt)[i]   = make_int4(0, 0, 0, 0);
    }
    if (blockIdx.x < 16) {                       // fused dtype detector
        int t = blockIdx.x * 256 + threadIdx.x;  // 4096 samples
        int stride = (2 * (NE / 4096));
        int vv = w[(unsigned)(t * stride + 1)];
        if (__syncthreads_or(vv != 0) && threadIdx.x == 0) atomicOr(&g_any, 1);
    }
}

// weighted degree (by src) + in-degree histogram (by dst); histogram atomic's
// return value IS the CSR rank. 2 edges per thread, vectorized loads.
__global__ void k_deg(const void* __restrict__ ei, const float2* __restrict__ ew2) {
    unsigned t = blockIdx.x * 256 + threadIdx.x;     // NE/2 threads
    unsigned e = t * 2;
    int s0, s1, d0, d1;
    if (g_is64) {
        const longlong2* p = (const longlong2*)ei;
        longlong2 sv = p[t];
        longlong2 dv = p[(NE / 2) + t];
        s0 = (int)sv.x & (NN - 1); s1 = (int)sv.y & (NN - 1);
        d0 = (int)dv.x & (NN - 1); d1 = (int)dv.y & (NN - 1);
    } else {
        const int2* p = (const int2*)ei;
        int2 sv = p[t];
        int2 dv = p[(NE / 2) + t];
        s0 = sv.x & (NN - 1); s1 = sv.y & (NN - 1);
        d0 = dv.x & (NN - 1); d1 = dv.y & (NN - 1);
    }
    float2 w = ew2[t];
    atomicAdd(&g_deg[s0], w.x);
    atomicAdd(&g_deg[s1], w.y);
    g_rank[e]     = atomicAdd(&g_cnt[d0], 1);
    g_rank[e + 1] = atomicAdd(&g_cnt[d1], 1);
}

// ---- parallel 2-launch exclusive scan of g_cnt -> g_off --------------------
// Phase A: 128 blocks x 1024 threads: block-local exclusive scan + block total
__global__ void __launch_bounds__(1024) k_scanA() {
    __shared__ int wsum[32];
    const int tid  = threadIdx.x;
    const int lane = tid & 31;
    const int w    = tid >> 5;
    const int gid  = blockIdx.x * 1024 + tid;
    int v = g_cnt[gid];
    int x = v;
#pragma unroll
    for (int d = 1; d < 32; d <<= 1) {
        int y = __shfl_up_sync(0xffffffffu, x, d);
        if (lane >= d) x += y;
    }
    if (lane == 31) wsum[w] = x;
    __syncthreads();
    if (w == 0) {
        int s = wsum[lane];
#pragma unroll
        for (int d = 1; d < 32; d <<= 1) {
            int y = __shfl_up_sync(0xffffffffu, s, d);
            if (lane >= d) s += y;
        }
        wsum[lane] = s;
    }
    __syncthreads();
    int incl = x + (w > 0 ? wsum[w - 1] : 0);
    g_off[gid] = incl - v;                     // block-local exclusive
    if (tid == 1023) g_bsum[blockIdx.x] = incl;
}

// Phase C (merged B): each block reduces its own bsum prefix and applies it.
// 512 blocks x 256 threads; block covers 256 g_off entries within ONE 1024-chunk.
__global__ void k_scanC() {
    __shared__ int wred[8];
    __shared__ int base_s, tot_s;
    const int tid  = threadIdx.x;
    const int lane = tid & 31;
    const int w    = tid >> 5;
    const int nb   = blockIdx.x >> 2;          // this block's bsum chunk index
    const bool last = (blockIdx.x == gridDim.x - 1);

    int bs = (tid < 128) ? g_bsum[tid] : 0;
    int vp = (tid < nb) ? bs : 0;              // masked: prefix sum
    int vf = last ? bs : 0;                    // full sum (last block only)
#pragma unroll
    for (int d = 16; d > 0; d >>= 1) {
        vp += __shfl_down_sync(0xffffffffu, vp, d);
        vf += __shfl_down_sync(0xffffffffu, vf, d);
    }
    if (lane == 0) wred[w] = vp;
    __syncthreads();
    if (tid == 0) {
        int p = 0;
#pragma unroll
        for (int i = 0; i < 8; i++) p += wred[i];
        base_s = p;
    }
    __syncthreads();
    if (last && lane == 0) wred[w] = vf;       // reuse after read barrier
    __syncthreads();
    if (last && tid == 0) {
        int tt = 0;
#pragma unroll
        for (int i = 0; i < 8; i++) tt += wred[i];
        tot_s = tt;
    }
    int gid = blockIdx.x * 256 + tid;
    g_off[gid] += base_s;
    if (last) {
        __syncthreads();
        if (tid == 0) g_off[NN] = tot_s;
    }
}

// scatter edges into packed CSR records — NO atomics (rank precomputed);
// dinv fused: rsqrt applied to raw degrees inline
__global__ void k_scatter(const void* __restrict__ ei, const float* __restrict__ ew) {
    unsigned e = blockIdx.x * 256 + threadIdx.x;
    if (e >= NE) return;
    int s = eidx(ei, e);
    int d = eidx(ei, NE + e);
    float ds = g_deg[s], dd = g_deg[d];
    float is = (ds > 0.f) ? rsqrtf(ds) : 0.f;
    float id = (dd > 0.f) ? rsqrtf(dd) : 0.f;
    float w = -is * ew[e] * id;
    unsigned pos = (unsigned)(g_off[d] + g_rank[e]) & (NE - 1);  // trap-proof
    g_edge[pos] = make_int2(s, __float_as_int(w));
}

// Pack B: reparametrized Chebyshev weights (Y_k = L^k x basis), transposed
// [n][k], fp16, SW128-pre-swizzled.  Thread 0 also latches the dtype flag.
//   B0 = W0 - W2 ; B1 = W1 - 3*W3 ; B2 = 2*W2 ; B3 = 4*W3
__global__ void k_pack(const float* __restrict__ Wx, const float* __restrict__ bx,
                       const float* __restrict__ bh) {
    int i = blockIdx.x * 256 + threadIdx.x;   // 65536 total
    if (i == 0) g_is64 = (g_any == 0);        // fused setflag
    int kb = i >> 14, n = (i >> 6) & 255, kk = i & 63;
    int g  = (n < 128) ? 0 : 2;
    int jj = n & 127;
    const size_t base = (size_t)g * 4 * 64 * 128 + (size_t)kk * 128 + jj;
    const size_t kstep = (size_t)64 * 128;
    float w;
    if      (kb == 0) w = Wx[base]             - Wx[base + 2 * kstep];
    else if (kb == 1) w = Wx[base + kstep]     - 3.f * Wx[base + 3 * kstep];
    else if (kb == 2) w = 2.f * Wx[base + 2 * kstep];
    else              w = 4.f * Wx[base + 3 * kstep];
    uint32_t off = SWZ128((uint32_t)(n * 128 + kk * 2));   // byte off in 32KB tile
    g_B[(uint32_t)kb * 16384 + (off >> 1)] = __float2half(w);
    if (kb == 0 && kk == 0) g_bias[n] = bx[g * 128 + jj] + bh[g * 128 + jj];
}

// ---------------- SpMM gather (fp16 rows): out[d] = sum_e w_e * vin[src_e] --
// One warp per dst node; 2 half-warps × unroll-4 = 8 edges in flight per warp.
__global__ void __launch_bounds__(256)
k_spmm(const uint2* __restrict__ vin, uint2* __restrict__ vout) {
    const int node = blockIdx.x * 8 + (threadIdx.x >> 5);
    const int lane = threadIdx.x & 31;
    const int lh   = lane & 15;
    const int half = lane >> 4;
    const int beg = g_off[node];
    const int end = g_off[node + 1];

    float4 acc = make_float4(0.f, 0.f, 0.f, 0.f);
    int i = beg + half;
    for (; i + 6 < end; i += 8) {        // 4 edges per half-warp in flight
        int2 e0 = g_edge[i];
        int2 e1 = g_edge[i + 2];
        int2 e2 = g_edge[i + 4];
        int2 e3 = g_edge[i + 6];
        acc_edge(acc, e0, vin, lh);
        acc_edge(acc, e1, vin, lh);
        acc_edge(acc, e2, vin, lh);
        acc_edge(acc, e3, vin, lh);
    }
    for (; i < end; i += 2) {
        int2 e0 = g_edge[i];
        acc_edge(acc, e0, vin, lh);
    }
    acc.x += __shfl_xor_sync(0xffffffffu, acc.x, 16);
    acc.y += __shfl_xor_sync(0xffffffffu, acc.y, 16);
    acc.z += __shfl_xor_sync(0xffffffffu, acc.z, 16);
    acc.w += __shfl_xor_sync(0xffffffffu, acc.w, 16);

    if (half == 0) {
        __half2 h01 = __floats2half2_rn(acc.x, acc.y);
        __half2 h23 = __floats2half2_rn(acc.z, acc.w);
        uint2 o;
        o.x = *reinterpret_cast<uint32_t*>(&h01);
        o.y = *reinterpret_cast<uint32_t*>(&h23);
        vout[(long)node * 16 + lh] = o;
    }
}

// ---------------- mma.sync GEMM [128 rows/CTA, N=256, K=256] + GRU epilogue -
// A fp16, B fp16; fp32 accum. cp.async double-buffered (round-8 proven config).
// SMEM (dynamic): [0..1024) row-reduce; A ping-pong @1024 (2x16KB);
//                 B ping-pong @33792 (2x32KB). Total 99328 B.
#define SM_A0  1024
#define SM_B0  33792
#define SM_DYN 99328

__global__ void __launch_bounds__(256, 1)
k_gemm_mma(const float* __restrict__ Wlin, const float* __restrict__ blin,
           float* __restrict__ outbuf) {
    extern __shared__ char smem[];
    float* smf = (float*)smem;               // [0..128) rs, [128..256) dt
    const uint32_t sb  = smem_u32(smem);
    const int tid  = threadIdx.x;
    const int wid  = tid >> 5;
    const int lane = tid & 31;
    const int wm   = wid & 3;                // m quarter: rows wm*32..+31
    const int wn   = wid >> 2;               // n half pattern
    const long rowBase = (long)blockIdx.x * 128;

    if (tid < 128) { smf[tid] = 0.f; smf[128 + tid] = 0.f; }

    const __half* bases[4] = { g_xh + rowBase * FI, g_Y1 + rowBase * FI,
                               g_Y2 + rowBase * FI, g_Y3 + rowBase * FI };

    // async stage of chunk c into buffer b (A swizzled on the fly, B pre-swizzled)
    auto stage = [&](int c, int b) {
        const uint4* Asrc = (const uint4*)bases[c];
        uint32_t abase = sb + SM_A0 + (uint32_t)b * 16384;
#pragma unroll
        for (int it = 0; it < 4; it++) {
            int idx = tid + it * 256;           // 1024 uint4
            int r  = idx >> 3;
            int c8 = idx & 7;
            cpa16(abase + (uint32_t)(r * 128 + ((c8 ^ (r & 7)) << 4)), Asrc + idx);
        }
        const uint4* Bsrc = (const uint4*)(g_B + (size_t)c * 16384);
        uint32_t bbase = sb + SM_B0 + (uint32_t)b * 32768;
#pragma unroll
        for (int it = 0; it < 8; it++) {
            int idx = tid + it * 256;           // 2048 uint4
            cpa16(bbase + (uint32_t)idx * 16, Bsrc + idx);
        }
        asm volatile("cp.async.commit_group;");
    };

    float acc[2][16][4];
#pragma unroll
    for (int mt = 0; mt < 2; mt++)
#pragma unroll
        for (int t = 0; t < 16; t++)
#pragma unroll
            for (int q = 0; q < 4; q++) acc[mt][t][q] = 0.f;

    stage(0, 0);

#pragma unroll 1
    for (int c = 0; c < 4; c++) {
        const int cur = c & 1;
        if (c < 3) {
            stage(c + 1, cur ^ 1);
            asm volatile("cp.async.wait_group 1;");
        } else {
            asm volatile("cp.async.wait_group 0;");
        }
        __syncthreads();

        const uint32_t Aoff = SM_A0 + (uint32_t)cur * 16384;
        const uint32_t Boff = SM_B0 + (uint32_t)cur * 32768;
#pragma unroll
        for (int ks = 0; ks < 4; ks++) {
            uint32_t a[2][4];
#pragma unroll
            for (int mt = 0; mt < 2; mt++) {
                int r = wm * 32 + mt * 16 + (lane & 15);
                int g = 2 * ks + (lane >> 4);
                uint32_t ad = sb + Aoff + (uint32_t)(r * 128 + ((g ^ (r & 7)) << 4));
                ldsm4(a[mt][0], a[mt][1], a[mt][2], a[mt][3], ad);
            }
#pragma unroll
            for (int p = 0; p < 8; p++) {
                int tix = (p < 4) ? (2 * p) : (8 + 2 * (p - 4));
                int ntb = wn * 8 + ((p < 4) ? (2 * p) : (16 + 2 * (p - 4)));
                int n = ntb * 8 + (lane & 7) + ((lane >> 4) << 3);
                int g = 2 * ks + ((lane >> 3) & 1);
                uint32_t bd = sb + Boff + (uint32_t)(n * 128 + ((g ^ (n & 7)) << 4));
                uint32_t b0, b1, b2, b3;
                ldsm4(b0, b1, b2, b3, bd);
                mma16816(acc[0][tix],     a[0], b0, b1);
                mma16816(acc[1][tix],     a[1], b0, b1);
                mma16816(acc[0][tix + 1], a[0], b2, b3);
                mma16816(acc[1][tix + 1], a[1], b2, b3);
            }
        }
        __syncthreads();
    }

    // ---- GRU epilogue on register accumulators (HW tanh) -------------------
    const float bl = __ldg(blin);
#pragma unroll
    for (int mt = 0; mt < 2; mt++) {
        float rs0 = 0.f, dt0 = 0.f, rs1 = 0.f, dt1 = 0.f;
#pragma unroll
        for (int i = 0; i < 8; i++) {
            int j0 = wn * 64 + i * 8 + 2 * (lane & 3);
            float bu0 = __ldg(g_bias + j0),       bu1 = __ldg(g_bias + j0 + 1);
            float bv0 = __ldg(g_bias + j0 + 128), bv1 = __ldg(g_bias + j0 + 129);
            float w0  = __ldg(Wlin + j0),         w1  = __ldg(Wlin + j0 + 1);
            float h00 = gru_h(acc[mt][i][0] + bu0, acc[mt][8 + i][0] + bv0);
            float h01 = gru_h(acc[mt][i][1] + bu1, acc[mt][8 + i][1] + bv1);
            float h10 = gru_h(acc[mt][i][2] + bu0, acc[mt][8 + i][2] + bv0);
            float h11 = gru_h(acc[mt][i][3] + bu1, acc[mt][8 + i][3] + bv1);
            rs0 += h00 + h01; dt0 = fmaf(h00, w0, fmaf(h01, w1, dt0));
            rs1 += h10 + h11; dt1 = fmaf(h10, w0, fmaf(h11, w1, dt1));
        }
#pragma unroll
        for (int s = 1; s < 4; s <<= 1) {
            rs0 += __shfl_xor_sync(0xffffffffu, rs0, s);
            dt0 += __shfl_xor_sync(0xffffffffu, dt0, s);
            rs1 += __shfl_xor_sync(0xffffffffu, rs1, s);
            dt1 += __shfl_xor_sync(0xffffffffu, dt1, s);
        }
        if ((lane & 3) == 0) {
            int r = wm * 32 + mt * 16 + (lane >> 2);
            atomicAdd(&smf[r],           rs0);
            atomicAdd(&smf[128 + r],     dt0);
            atomicAdd(&smf[r + 8],       rs1);
            atomicAdd(&smf[128 + r + 8], dt1);
        }
    }
    __syncthreads();
    if (tid < 128) {
        long grow = rowBase + tid;
        outbuf[grow]      = smf[128 + tid] + bl;   // out = h @ W_lin + b_lin
        outbuf[NN + grow] = sqrtf(smf[tid]);       // logits = sqrt(rowsum(relu(H)))
    }
}

// ---------------- launch orchestration -------------------------------------
extern "C" void kernel_launch(void* const* d_in, const int* in_sizes, int n_in,
                              void* d_out, int out_size) {
    const float* x  = (const float*)d_in[0];
    const void*  ei = d_in[1];                 // int32 or int64 — detected on device
    const float* ew = (const float*)d_in[2];
    const float* Wx = (const float*)d_in[3];
    // d_in[4] = W_h : provably unused (H==0 => cheb(H,*) == bias)
    const float* bx = (const float*)d_in[5];
    const float* bh = (const float*)d_in[6];
    const float* Wl = (const float*)d_in[7];
    const float* bl = (const float*)d_in[8];
    float* out = (float*)d_out;
    (void)in_sizes; (void)n_in; (void)out_size;

    void *pXh, *pY1, *pY2, *pY3;
    cudaGetSymbolAddress(&pXh, g_xh);
    cudaGetSymbolAddress(&pY1, g_Y1);
    cudaGetSymbolAddress(&pY2, g_Y2);
    cudaGetSymbolAddress(&pY3, g_Y3);

    cudaFuncSetAttribute(k_gemm_mma, cudaFuncAttributeMaxDynamicSharedMemorySize, SM_DYN);

    // ---- prep: xcast(+zero+detect) -> pack(+setflag) -> deg -> scanA/C -> scatter
    k_xcast  <<<(NN * FI / 4) / 256, 256>>>((const float4*)x, (const int*)ei);
    k_pack   <<<256, 256>>>(Wx, bx, bh);   // also latches g_is64
    k_deg    <<<(NE / 2) / 256, 256>>>(ei, (const float2*)ew);
    k_scanA  <<<NN / 1024, 1024>>>();
    k_scanC  <<<NN / 256, 256>>>();        // merged B+C
    k_scatter<<<NE / 256, 256>>>(ei, ew);  // dinv fused (rsqrt inline)

    // ---- power basis: Y1 = L x ; Y2 = L Y1 ; Y3 = L Y2   (fp16 storage)
    k_spmm<<<NN / 8, 256>>>((const uint2*)pXh, (uint2*)pY1);
    k_spmm<<<NN / 8, 256>>>((const uint2*)pY1, (uint2*)pY2);
    k_spmm<<<NN / 8, 256>>>((const uint2*)pY2, (uint2*)pY3);

    // ---- fused mma.sync GEMM + GRU + head
    k_gemm_mma<<<NN / 128, 256, SM_DYN>>>(Wl, bl, out);
}

// round 16
// speedup vs baseline: 1.3128x; 1.0042x over previous
#include <cuda_runtime.h>
#include <cuda_fp16.h>
#include <cstdint>

#define NN 131072
#define NE 4194304
#define FI 64

// ---------------- scratch (device globals: no allocation allowed) ----------
__device__ float  g_deg [NN];        // raw weighted degree (by src)
__device__ int    g_cnt [NN];        // in-degree histogram (by dst)
__device__ int    g_off [NN + 1];    // CSR row offsets (by dst)
__device__ int    g_bsum[128];       // per-scan-block totals
__device__ int    g_rank[NE];        // per-edge rank within its dst row
__device__ int2   g_edge[NE];        // CSR record: {src, weight-bits}
__device__ __half g_xh[NN * FI];     // x cast to fp16
__device__ __half g_Y1[NN * FI];     // Y1 = L x
__device__ __half g_Y2[NN * FI];     // Y2 = L Y1
__device__ __half g_Y3[NN * FI];     // Y3 = L Y2
// B operand [chunk kb][n 0..255][k 0..63] fp16, SW128-pre-swizzled (32KB/chunk)
__device__ __half g_B[4 * 256 * 64];
__device__ float  g_bias[256];       // b_x[g]+b_h[g] for gate0|gate2
__device__ int    g_any;             // static-zero init; idempotent OR across runs
                                     // g_any==0  <=>  edge_index is int64

// ---------------- edge-index access (dtype-robust, trap-proof) -------------
__device__ __forceinline__ int eidx(const void* ei, unsigned i) {
    int v;
    if (g_any == 0) v = (int)((const long long*)ei)[i];   // int64 layout
    else            v = ((const int*)ei)[i];              // int32 layout
    return v & (NN - 1);             // NN = 2^17: no-op for valid ids, trap-proof
}

// ---------------- helpers ----------------------------------------------------
__device__ __forceinline__ uint32_t smem_u32(const void* p) {
    uint32_t a;
    asm("{ .reg .u64 t; cvta.to.shared.u64 t, %1; cvt.u32.u64 %0, t; }"
        : "=r"(a) : "l"(p));
    return a;
}
#define SWZ128(o) ((o) ^ (((o) >> 3) & 0x70))

__device__ __forceinline__ void ldsm4(uint32_t& r0, uint32_t& r1, uint32_t& r2,
                                      uint32_t& r3, uint32_t addr) {
    asm volatile("ldmatrix.sync.aligned.m8n8.x4.shared.b16 {%0,%1,%2,%3}, [%4];"
                 : "=r"(r0), "=r"(r1), "=r"(r2), "=r"(r3) : "r"(addr));
}
__device__ __forceinline__ void mma16816(float* c, const uint32_t* a,
                                         uint32_t b0, uint32_t b1) {
    asm volatile("mma.sync.aligned.m16n8k16.row.col.f32.f16.f16.f32 "
                 "{%0,%1,%2,%3}, {%4,%5,%6,%7}, {%8,%9}, {%0,%1,%2,%3};"
                 : "+f"(c[0]), "+f"(c[1]), "+f"(c[2]), "+f"(c[3])
                 : "r"(a[0]), "r"(a[1]), "r"(a[2]), "r"(a[3]), "r"(b0), "r"(b1));
}
__device__ __forceinline__ void cpa16(uint32_t dst, const void* src) {
    asm volatile("cp.async.cg.shared.global [%0], [%1], 16;"
                 :: "r"(dst), "l"(src));
}
__device__ __forceinline__ float tanh_hw(float x) {
    float y;
    asm("tanh.approx.f32 %0, %1;" : "=f"(y) : "f"(x));
    return y;
}
// H = (1 - sigmoid(u)) * tanh(v), relu'd.
// 1 - sigmoid(u) = 0.5 - 0.5*tanh(u/2)  ->  2 HW tanh + 2 FMA
__device__ __forceinline__ float gru_h(float u, float v) {
    float z1 = fmaf(-0.5f, tanh_hw(0.5f * u), 0.5f);
    return fmaxf(z1 * tanh_hw(v), 0.f);
}
__device__ __forceinline__ void acc_edge(float4& acc, int2 e,
                                         const uint2* __restrict__ vin, int lh) {
    uint2 u = vin[(long)e.x * 16 + lh];
    float w = __int_as_float(e.y);
    float2 f0 = __half22float2(*reinterpret_cast<__half2*>(&u.x));
    float2 f1 = __half22float2(*reinterpret_cast<__half2*>(&u.y));
    acc.x = fmaf(w, f0.x, acc.x); acc.y = fmaf(w, f0.y, acc.y);
    acc.z = fmaf(w, f1.x, acc.z); acc.w = fmaf(w, f1.y, acc.w);
}

// ---------------- prep kernels ---------------------------------------------
// zero g_deg/g_cnt (128 blocks x 256 = 32768 threads, float4/int4) and
// sample odd 32-bit words of the first 2*NE edge-index words (blocks 0..15):
// all-zero <=> int64 layout.  g_any is static-zero + idempotent OR.
__global__ void k_detect(const int* __restrict__ w) {
    int i = blockIdx.x * 256 + threadIdx.x;      // 32768 threads = NN/4 vec4
    ((float4*)g_deg)[i] = make_float4(0.f, 0.f, 0.f, 0.f);
    ((int4*)g_cnt)[i]   = make_int4(0, 0, 0, 0);
    if (blockIdx.x < 16) {                       // 4096 samples
        int stride = (2 * (NE / 4096));
        int vv = w[(unsigned)(i * stride + 1)];
        if (__syncthreads_or(vv != 0) && threadIdx.x == 0) atomicOr(&g_any, 1);
    }
}

// x -> fp16 cast (pure; runs on side stream)
__global__ void k_xcast(const float4* __restrict__ x) {
    int i = blockIdx.x * 256 + threadIdx.x;      // NN*FI/4 threads
    float4 v = x[i];
    __half2 a = __floats2half2_rn(v.x, v.y);
    __half2 b = __floats2half2_rn(v.z, v.w);
    uint2 o;
    o.x = *reinterpret_cast<uint32_t*>(&a);
    o.y = *reinterpret_cast<uint32_t*>(&b);
    *reinterpret_cast<uint2*>(g_xh + (size_t)i * 4) = o;
}

// weighted degree (by src) + in-degree histogram (by dst); histogram atomic's
// return value IS the CSR rank. 2 edges per thread, vectorized loads.
__global__ void k_deg(const void* __restrict__ ei, const float2* __restrict__ ew2) {
    unsigned t = blockIdx.x * 256 + threadIdx.x;     // NE/2 threads
    unsigned e = t * 2;
    int s0, s1, d0, d1;
    if (g_any == 0) {                                // int64 layout
        const longlong2* p = (const longlong2*)ei;
        longlong2 sv = p[t];
        longlong2 dv = p[(NE / 2) + t];
        s0 = (int)sv.x & (NN - 1); s1 = (int)sv.y & (NN - 1);
        d0 = (int)dv.x & (NN - 1); d1 = (int)dv.y & (NN - 1);
    } else {
        const int2* p = (const int2*)ei;
        int2 sv = p[t];
        int2 dv = p[(NE / 2) + t];
        s0 = sv.x & (NN - 1); s1 = sv.y & (NN - 1);
        d0 = dv.x & (NN - 1); d1 = dv.y & (NN - 1);
    }
    float2 w = ew2[t];
    atomicAdd(&g_deg[s0], w.x);
    atomicAdd(&g_deg[s1], w.y);
    g_rank[e]     = atomicAdd(&g_cnt[d0], 1);
    g_rank[e + 1] = atomicAdd(&g_cnt[d1], 1);
}

// ---- parallel 2-launch exclusive scan of g_cnt -> g_off --------------------
// Phase A: 128 blocks x 1024 threads: block-local exclusive scan + block total
__global__ void __launch_bounds__(1024) k_scanA() {
    __shared__ int wsum[32];
    const int tid  = threadIdx.x;
    const int lane = tid & 31;
    const int w    = tid >> 5;
    const int gid  = blockIdx.x * 1024 + tid;
    int v = g_cnt[gid];
    int x = v;
#pragma unroll
    for (int d = 1; d < 32; d <<= 1) {
        int y = __shfl_up_sync(0xffffffffu, x, d);
        if (lane >= d) x += y;
    }
    if (lane == 31) wsum[w] = x;
    __syncthreads();
    if (w == 0) {
        int s = wsum[lane];
#pragma unroll
        for (int d = 1; d < 32; d <<= 1) {
            int y = __shfl_up_sync(0xffffffffu, s, d);
            if (lane >= d) s += y;
        }
        wsum[lane] = s;
    }
    __syncthreads();
    int incl = x + (w > 0 ? wsum[w - 1] : 0);
    g_off[gid] = incl - v;                     // block-local exclusive
    if (tid == 1023) g_bsum[blockIdx.x] = incl;
}

// Phase C (merged B): each block reduces its own bsum prefix and applies it.
__global__ void k_scanC() {
    __shared__ int wred[8];
    __shared__ int base_s, tot_s;
    const int tid  = threadIdx.x;
    const int lane = tid & 31;
    const int w    = tid >> 5;
    const int nb   = blockIdx.x >> 2;          // this block's bsum chunk index
    const bool last = (blockIdx.x == gridDim.x - 1);

    int bs = (tid < 128) ? g_bsum[tid] : 0;
    int vp = (tid < nb) ? bs : 0;              // masked: prefix sum
    int vf = last ? bs : 0;                    // full sum (last block only)
#pragma unroll
    for (int d = 16; d > 0; d >>= 1) {
        vp += __shfl_down_sync(0xffffffffu, vp, d);
        vf += __shfl_down_sync(0xffffffffu, vf, d);
    }
    if (lane == 0) wred[w] = vp;
    __syncthreads();
    if (tid == 0) {
        int p = 0;
#pragma unroll
        for (int i = 0; i < 8; i++) p += wred[i];
        base_s = p;
    }
    __syncthreads();
    if (last && lane == 0) wred[w] = vf;       // reuse after read barrier
    __syncthreads();
    if (last && tid == 0) {
        int tt = 0;
#pragma unroll
        for (int i = 0; i < 8; i++) tt += wred[i];
        tot_s = tt;
    }
    int gid = blockIdx.x * 256 + tid;
    g_off[gid] += base_s;
    if (last) {
        __syncthreads();
        if (tid == 0) g_off[NN] = tot_s;
    }
}

// scatter edges into packed CSR records — NO atomics (rank precomputed);
// dinv fused: rsqrt applied to raw degrees inline
__global__ void k_scatter(const void* __restrict__ ei, const float* __restrict__ ew) {
    unsigned e = blockIdx.x * 256 + threadIdx.x;
    if (e >= NE) return;
    int s = eidx(ei, e);
    int d = eidx(ei, NE + e);
    float ds = g_deg[s], dd = g_deg[d];
    float is = (ds > 0.f) ? rsqrtf(ds) : 0.f;
    float id = (dd > 0.f) ? rsqrtf(dd) : 0.f;
    float w = -is * ew[e] * id;
    unsigned pos = (unsigned)(g_off[d] + g_rank[e]) & (NE - 1);  // trap-proof
    g_edge[pos] = make_int2(s, __float_as_int(w));
}

// Pack B: reparametrized Chebyshev weights (Y_k = L^k x basis), transposed
// [n][k], fp16, SW128-pre-swizzled.  (side stream; no edge deps)
//   B0 = W0 - W2 ; B1 = W1 - 3*W3 ; B2 = 2*W2 ; B3 = 4*W3
__global__ void k_pack(const float* __restrict__ Wx, const float* __restrict__ bx,
                       const float* __restrict__ bh) {
    int i = blockIdx.x * 256 + threadIdx.x;   // 65536 total
    int kb = i >> 14, n = (i >> 6) & 255, kk = i & 63;
    int g  = (n < 128) ? 0 : 2;
    int jj = n & 127;
    const size_t base = (size_t)g * 4 * 64 * 128 + (size_t)kk * 128 + jj;
    const size_t kstep = (size_t)64 * 128;
    float w;
    if      (kb == 0) w = Wx[base]             - Wx[base + 2 * kstep];
    else if (kb == 1) w = Wx[base + kstep]     - 3.f * Wx[base + 3 * kstep];
    else if (kb == 2) w = 2.f * Wx[base + 2 * kstep];
    else              w = 4.f * Wx[base + 3 * kstep];
    uint32_t off = SWZ128((uint32_t)(n * 128 + kk * 2));   // byte off in 32KB tile
    g_B[(uint32_t)kb * 16384 + (off >> 1)] = __float2half(w);
    if (kb == 0 && kk == 0) g_bias[n] = bx[g * 128 + jj] + bh[g * 128 + jj];
}

// ---------------- SpMM gather (fp16 rows): out[d] = sum_e w_e * vin[src_e] --
// One warp per dst node; 2 half-warps × unroll-4 = 8 edges in flight per warp.
__global__ void __launch_bounds__(256)
k_spmm(const uint2* __restrict__ vin, uint2* __restrict__ vout) {
    const int node = blockIdx.x * 8 + (threadIdx.x >> 5);
    const int lane = threadIdx.x & 31;
    const int lh   = lane & 15;
    const int half = lane >> 4;
    const int beg = g_off[node];
    const int end = g_off[node + 1];

    float4 acc = make_float4(0.f, 0.f, 0.f, 0.f);
    int i = beg + half;
    for (; i + 6 < end; i += 8) {        // 4 edges per half-warp in flight
        int2 e0 = g_edge[i];
        int2 e1 = g_edge[i + 2];
        int2 e2 = g_edge[i + 4];
        int2 e3 = g_edge[i + 6];
        acc_edge(acc, e0, vin, lh);
        acc_edge(acc, e1, vin, lh);
        acc_edge(acc, e2, vin, lh);
        acc_edge(acc, e3, vin, lh);
    }
    for (; i < end; i += 2) {
        int2 e0 = g_edge[i];
        acc_edge(acc, e0, vin, lh);
    }
    acc.x += __shfl_xor_sync(0xffffffffu, acc.x, 16);
    acc.y += __shfl_xor_sync(0xffffffffu, acc.y, 16);
    acc.z += __shfl_xor_sync(0xffffffffu, acc.z, 16);
    acc.w += __shfl_xor_sync(0xffffffffu, acc.w, 16);

    if (half == 0) {
        __half2 h01 = __floats2half2_rn(acc.x, acc.y);
        __half2 h23 = __floats2half2_rn(acc.z, acc.w);
        uint2 o;
        o.x = *reinterpret_cast<uint32_t*>(&h01);
        o.y = *reinterpret_cast<uint32_t*>(&h23);
        vout[(long)node * 16 + lh] = o;
    }
}

// ---------------- mma.sync GEMM [128 rows/CTA, N=256, K=256] + GRU epilogue -
// A fp16, B fp16; fp32 accum. cp.async double-buffered (round-8 proven config).
// SMEM (dynamic): [0..1024) row-reduce; A ping-pong @1024 (2x16KB);
//                 B ping-pong @33792 (2x32KB). Total 99328 B.
#define SM_A0  1024
#define SM_B0  33792
#define SM_DYN 99328

__global__ void __launch_bounds__(256, 1)
k_gemm_mma(const float* __restrict__ Wlin, const float* __restrict__ blin,
           float* __restrict__ outbuf) {
    extern __shared__ char smem[];
    float* smf = (float*)smem;               // [0..128) rs, [128..256) dt
    const uint32_t sb  = smem_u32(smem);
    const int tid  = threadIdx.x;
    const int wid  = tid >> 5;
    const int lane = tid & 31;
    const int wm   = wid & 3;                // m quarter: rows wm*32..+31
    const int wn   = wid >> 2;               // n half pattern
    const long rowBase = (long)blockIdx.x * 128;

    if (tid < 128) { smf[tid] = 0.f; smf[128 + tid] = 0.f; }

    const __half* bases[4] = { g_xh + rowBase * FI, g_Y1 + rowBase * FI,
                               g_Y2 + rowBase * FI, g_Y3 + rowBase * FI };

    // async stage of chunk c into buffer b (A swizzled on the fly, B pre-swizzled)
    auto stage = [&](int c, int b) {
        const uint4* Asrc = (const uint4*)bases[c];
        uint32_t abase = sb + SM_A0 + (uint32_t)b * 16384;
#pragma unroll
        for (int it = 0; it < 4; it++) {
            int idx = tid + it * 256;           // 1024 uint4
            int r  = idx >> 3;
            int c8 = idx & 7;
            cpa16(abase + (uint32_t)(r * 128 + ((c8 ^ (r & 7)) << 4)), Asrc + idx);
        }
        const uint4* Bsrc = (const uint4*)(g_B + (size_t)c * 16384);
        uint32_t bbase = sb + SM_B0 + (uint32_t)b * 32768;
#pragma unroll
        for (int it = 0; it < 8; it++) {
            int idx = tid + it * 256;           // 2048 uint4
            cpa16(bbase + (uint32_t)idx * 16, Bsrc + idx);
        }
        asm volatile("cp.async.commit_group;");
    };

    float acc[2][16][4];
#pragma unroll
    for (int mt = 0; mt < 2; mt++)
#pragma unroll
        for (int t = 0; t < 16; t++)
#pragma unroll
            for (int q = 0; q < 4; q++) acc[mt][t][q] = 0.f;

    stage(0, 0);

#pragma unroll 1
    for (int c = 0; c < 4; c++) {
        const int cur = c & 1;
        if (c < 3) {
            stage(c + 1, cur ^ 1);
            asm volatile("cp.async.wait_group 1;");
        } else {
            asm volatile("cp.async.wait_group 0;");
        }
        __syncthreads();

        const uint32_t Aoff = SM_A0 + (uint32_t)cur * 16384;
        const uint32_t Boff = SM_B0 + (uint32_t)cur * 32768;
#pragma unroll
        for (int ks = 0; ks < 4; ks++) {
            uint32_t a[2][4];
#pragma unroll
            for (int mt = 0; mt < 2; mt++) {
                int r = wm * 32 + mt * 16 + (lane & 15);
                int g = 2 * ks + (lane >> 4);
                uint32_t ad = sb + Aoff + (uint32_t)(r * 128 + ((g ^ (r & 7)) << 4));
                ldsm4(a[mt][0], a[mt][1], a[mt][2], a[mt][3], ad);
            }
#pragma unroll
            for (int p = 0; p < 8; p++) {
                int tix = (p < 4) ? (2 * p) : (8 + 2 * (p - 4));
                int ntb = wn * 8 + ((p < 4) ? (2 * p) : (16 + 2 * (p - 4)));
                int n = ntb * 8 + (lane & 7) + ((lane >> 4) << 3);
                int g = 2 * ks + ((lane >> 3) & 1);
                uint32_t bd = sb + Boff + (uint32_t)(n * 128 + ((g ^ (n & 7)) << 4));
                uint32_t b0, b1, b2, b3;
                ldsm4(b0, b1, b2, b3, bd);
                mma16816(acc[0][tix],     a[0], b0, b1);
                mma16816(acc[1][tix],     a[1], b0, b1);
                mma16816(acc[0][tix + 1], a[0], b2, b3);
                mma16816(acc[1][tix + 1], a[1], b2, b3);
            }
        }
        __syncthreads();
    }

    // ---- GRU epilogue on register accumulators (HW tanh) -------------------
    const float bl = __ldg(blin);
#pragma unroll
    for (int mt = 0; mt < 2; mt++) {
        float rs0 = 0.f, dt0 = 0.f, rs1 = 0.f, dt1 = 0.f;
#pragma unroll
        for (int i = 0; i < 8; i++) {
            int j0 = wn * 64 + i * 8 + 2 * (lane & 3);
            float bu0 = __ldg(g_bias + j0),       bu1 = __ldg(g_bias + j0 + 1);
            float bv0 = __ldg(g_bias + j0 + 128), bv1 = __ldg(g_bias + j0 + 129);
            float w0  = __ldg(Wlin + j0),         w1  = __ldg(Wlin + j0 + 1);
            float h00 = gru_h(acc[mt][i][0] + bu0, acc[mt][8 + i][0] + bv0);
            float h01 = gru_h(acc[mt][i][1] + bu1, acc[mt][8 + i][1] + bv1);
            float h10 = gru_h(acc[mt][i][2] + bu0, acc[mt][8 + i][2] + bv0);
            float h11 = gru_h(acc[mt][i][3] + bu1, acc[mt][8 + i][3] + bv1);
            rs0 += h00 + h01; dt0 = fmaf(h00, w0, fmaf(h01, w1, dt0));
            rs1 += h10 + h11; dt1 = fmaf(h10, w0, fmaf(h11, w1, dt1));
        }
#pragma unroll
        for (int s = 1; s < 4; s <<= 1) {
            rs0 += __shfl_xor_sync(0xffffffffu, rs0, s);
            dt0 += __shfl_xor_sync(0xffffffffu, dt0, s);
            rs1 += __shfl_xor_sync(0xffffffffu, rs1, s);
            dt1 += __shfl_xor_sync(0xffffffffu, dt1, s);
        }
        if ((lane & 3) == 0) {
            int r = wm * 32 + mt * 16 + (lane >> 2);
            atomicAdd(&smf[r],           rs0);
            atomicAdd(&smf[128 + r],     dt0);
            atomicAdd(&smf[r + 8],       rs1);
            atomicAdd(&smf[128 + r + 8], dt1);
        }
    }
    __syncthreads();
    if (tid < 128) {
        long grow = rowBase + tid;
        outbuf[grow]      = smf[128 + tid] + bl;   // out = h @ W_lin + b_lin
        outbuf[NN + grow] = sqrtf(smf[tid]);       // logits = sqrt(rowsum(relu(H)))
    }
}

// ---------------- launch orchestration -------------------------------------
extern "C" void kernel_launch(void* const* d_in, const int* in_sizes, int n_in,
                              void* d_out, int out_size) {
    const float* x  = (const float*)d_in[0];
    const void*  ei = d_in[1];                 // int32 or int64 — detected on device
    const float* ew = (const float*)d_in[2];
    const float* Wx = (const float*)d_in[3];
    // d_in[4] = W_h : provably unused (H==0 => cheb(H,*) == bias)
    const float* bx = (const float*)d_in[5];
    const float* bh = (const float*)d_in[6];
    const float* Wl = (const float*)d_in[7];
    const float* bl = (const float*)d_in[8];
    float* out = (float*)d_out;
    (void)in_sizes; (void)n_in; (void)out_size;

    void *pXh, *pY1, *pY2, *pY3;
    cudaGetSymbolAddress(&pXh, g_xh);
    cudaGetSymbolAddress(&pY1, g_Y1);
    cudaGetSymbolAddress(&pY2, g_Y2);
    cudaGetSymbolAddress(&pY3, g_Y3);

    cudaFuncSetAttribute(k_gemm_mma, cudaFuncAttributeMaxDynamicSharedMemorySize, SM_DYN);

    // fork/join side stream (fresh per call: deterministic DAG, no statics)
    cudaStream_t s1;
    cudaEvent_t eFork, eJoin;
    cudaStreamCreateWithFlags(&s1, cudaStreamNonBlocking);
    cudaEventCreateWithFlags(&eFork, cudaEventDisableTiming);
    cudaEventCreateWithFlags(&eJoin, cudaEventDisableTiming);

    // ---- main stream: detect(+zero) -> deg -> scanA -> scanC -> scatter
    k_detect<<<128, 256>>>((const int*)ei);
    cudaEventRecord(eFork, 0);
    cudaStreamWaitEvent(s1, eFork, 0);

    // ---- side stream (independent of edge pipeline): xcast, pack
    k_xcast<<<(NN * FI / 4) / 256, 256, 0, s1>>>((const float4*)x);
    k_pack <<<256, 256, 0, s1>>>(Wx, bx, bh);
    cudaEventRecord(eJoin, s1);

    k_deg    <<<(NE / 2) / 256, 256>>>(ei, (const float2*)ew);
    k_scanA  <<<NN / 1024, 1024>>>();
    k_scanC  <<<NN / 256, 256>>>();
    k_scatter<<<NE / 256, 256>>>(ei, ew);  // dinv fused (rsqrt inline)

    // join before SpMM (needs g_xh) / GEMM (needs g_B)
    cudaStreamWaitEvent(0, eJoin, 0);

    // ---- power basis: Y1 = L x ; Y2 = L Y1 ; Y3 = L Y2   (fp16 storage)
    k_spmm<<<NN / 8, 256>>>((const uint2*)pXh, (uint2*)pY1);
    k_spmm<<<NN / 8, 256>>>((const uint2*)pY1, (uint2*)pY2);
    k_spmm<<<NN / 8, 256>>>((const uint2*)pY2, (uint2*)pY3);

    // ---- fused mma.sync GEMM + GRU + head
    k_gemm_mma<<<NN / 128, 256, SM_DYN>>>(Wl, bl, out);
}